// round 2
// baseline (speedup 1.0000x reference)
#include <cuda_runtime.h>

#define N_NODES 100000
#define FEAT    128
#define CLS     64

// Scratch (allocation-free rule: __device__ globals)
__device__ float g_agg[(size_t)N_NODES * FEAT];   // aggregation accumulator / mean
__device__ float g_h[(size_t)N_NODES * FEAT];     // layer-1 activations
__device__ float g_cnt[N_NODES];                  // in-degree counts (float)

// ---------------------------------------------------------------------------
// Zero the accumulator (and counts on layer 1). Grid-stride float4 stores.
// ---------------------------------------------------------------------------
__global__ void zero_kernel(int zero_cnt) {
    int idx = blockIdx.x * blockDim.x + threadIdx.x;
    int stride = gridDim.x * blockDim.x;
    const int total = N_NODES * (FEAT / 4);
    float4* p = (float4*)g_agg;
    float4 z = make_float4(0.f, 0.f, 0.f, 0.f);
    for (int i = idx; i < total; i += stride) p[i] = z;
    if (zero_cnt) {
        for (int i = idx; i < N_NODES; i += stride) g_cnt[i] = 0.f;
    }
}

// ---------------------------------------------------------------------------
// Edge scatter: one warp per edge. Gather 128 floats of the source row as
// float4, vector-atomic-add into the destination row. Layer 1 also counts
// in-degree (lane 0). Indices are int32 (JAX x64 disabled downcasts int64).
// Bounds-guarded so a dtype surprise shows up as rel_err, not a crash.
// ---------------------------------------------------------------------------
__global__ void scatter_kernel(const float* __restrict__ x,
                               const int* __restrict__ srcs,
                               const int* __restrict__ dsts,
                               int n_edges, int layer1) {
    int gt   = blockIdx.x * blockDim.x + threadIdx.x;
    int e    = gt >> 5;
    int lane = gt & 31;
    if (e >= n_edges) return;
    int s = __ldg(srcs + e);
    int d = __ldg(dsts + e);
    if ((unsigned)s >= N_NODES || (unsigned)d >= N_NODES) return;
    const float* feat = layer1 ? x : g_h;
    float4 v = __ldg((const float4*)(feat + (size_t)s * FEAT) + lane);
    float* out = g_agg + (size_t)d * FEAT + lane * 4;
    asm volatile("red.global.add.v4.f32 [%0], {%1,%2,%3,%4};"
                 :: "l"(out), "f"(v.x), "f"(v.y), "f"(v.z), "f"(v.w)
                 : "memory");
    if (layer1 && lane == 0) atomicAdd(g_cnt + d, 1.0f);
}

// ---------------------------------------------------------------------------
// Scale accumulator rows by 1/max(cnt,1) in place (mean aggregation).
// ---------------------------------------------------------------------------
__global__ void scale_kernel() {
    int idx = blockIdx.x * blockDim.x + threadIdx.x;
    const int total = N_NODES * (FEAT / 4);
    if (idx >= total) return;
    int row = idx >> 5;                 // FEAT/4 = 32 float4 per row
    float inv = 1.0f / fmaxf(g_cnt[row], 1.0f);
    float4* p = (float4*)g_agg;
    float4 v = p[idx];
    v.x *= inv; v.y *= inv; v.z *= inv; v.w *= inv;
    p[idx] = v;
}

// ---------------------------------------------------------------------------
// GEMM1: h = relu([mean | x] @ [W1l; W1r]^T + b1l)
//   M = N_NODES, N = 128, K = 256 (concat). BM=128, BN=128, BK=16, 256 thr,
//   8x8 register tile per thread.
// ---------------------------------------------------------------------------
#define BM 128
#define BK 16

__global__ __launch_bounds__(256, 2)
void gemm1_kernel(const float* __restrict__ x,
                  const float* __restrict__ W1l,
                  const float* __restrict__ b1l,
                  const float* __restrict__ W1r) {
    __shared__ float As[BK][BM];
    __shared__ float Bs[BK][128];

    int t  = threadIdx.x;
    int m0 = blockIdx.x * BM;
    int tx = t & 15, ty = t >> 4;       // 16 x 16 thread grid

    float acc[8][8];
#pragma unroll
    for (int i = 0; i < 8; i++)
#pragma unroll
        for (int j = 0; j < 8; j++) acc[i][j] = 0.f;

    int la_m = t >> 1;                  // 0..127
    int la_k = (t & 1) * 8;             // 0 or 8
    int lb_n = t >> 1;
    int lb_k = (t & 1) * 8;

    for (int kt = 0; kt < 256; kt += BK) {
        const float* Asrc = (kt < 128) ? g_agg : x;
        int ak = (kt < 128) ? kt : (kt - 128);
        int m  = m0 + la_m;
        float4 a0, a1;
        if (m < N_NODES) {
            const float4* ap = (const float4*)(Asrc + (size_t)m * FEAT + ak + la_k);
            a0 = __ldg(ap); a1 = __ldg(ap + 1);
        } else {
            a0 = make_float4(0.f, 0.f, 0.f, 0.f); a1 = a0;
        }
        const float* Wsrc = (kt < 128) ? W1l : W1r;
        const float4* bp = (const float4*)(Wsrc + lb_n * FEAT + ak + lb_k);
        float4 b0 = __ldg(bp), b1 = __ldg(bp + 1);

        __syncthreads();
        As[la_k + 0][la_m] = a0.x; As[la_k + 1][la_m] = a0.y;
        As[la_k + 2][la_m] = a0.z; As[la_k + 3][la_m] = a0.w;
        As[la_k + 4][la_m] = a1.x; As[la_k + 5][la_m] = a1.y;
        As[la_k + 6][la_m] = a1.z; As[la_k + 7][la_m] = a1.w;
        Bs[lb_k + 0][lb_n] = b0.x; Bs[lb_k + 1][lb_n] = b0.y;
        Bs[lb_k + 2][lb_n] = b0.z; Bs[lb_k + 3][lb_n] = b0.w;
        Bs[lb_k + 4][lb_n] = b1.x; Bs[lb_k + 5][lb_n] = b1.y;
        Bs[lb_k + 6][lb_n] = b1.z; Bs[lb_k + 7][lb_n] = b1.w;
        __syncthreads();

#pragma unroll
        for (int k = 0; k < BK; k++) {
            float a[8], b[8];
            *(float4*)(a)     = *(const float4*)&As[k][ty * 8];
            *(float4*)(a + 4) = *(const float4*)&As[k][ty * 8 + 4];
            *(float4*)(b)     = *(const float4*)&Bs[k][tx * 8];
            *(float4*)(b + 4) = *(const float4*)&Bs[k][tx * 8 + 4];
#pragma unroll
            for (int i = 0; i < 8; i++)
#pragma unroll
                for (int j = 0; j < 8; j++)
                    acc[i][j] = fmaf(a[i], b[j], acc[i][j]);
        }
    }

    float bias[8];
    *(float4*)(bias)     = __ldg((const float4*)(b1l + tx * 8));
    *(float4*)(bias + 4) = __ldg((const float4*)(b1l + tx * 8 + 4));

#pragma unroll
    for (int i = 0; i < 8; i++) {
        int m = m0 + ty * 8 + i;
        if (m < N_NODES) {
            float4 o0, o1;
            o0.x = fmaxf(acc[i][0] + bias[0], 0.f);
            o0.y = fmaxf(acc[i][1] + bias[1], 0.f);
            o0.z = fmaxf(acc[i][2] + bias[2], 0.f);
            o0.w = fmaxf(acc[i][3] + bias[3], 0.f);
            o1.x = fmaxf(acc[i][4] + bias[4], 0.f);
            o1.y = fmaxf(acc[i][5] + bias[5], 0.f);
            o1.z = fmaxf(acc[i][6] + bias[6], 0.f);
            o1.w = fmaxf(acc[i][7] + bias[7], 0.f);
            float4* hp = (float4*)(g_h + (size_t)m * FEAT + tx * 8);
            hp[0] = o0; hp[1] = o1;
        }
    }
}

// ---------------------------------------------------------------------------
// GEMM2: out = log_softmax([mean2 | h] @ [W2l; W2r]^T + b2l)
//   M = N_NODES, N = 64, K = 256. BM=128, BN=64, 256 thr, 8x4 tile.
//   Row log_softmax via 16-lane shuffle reduction.
// ---------------------------------------------------------------------------
__global__ __launch_bounds__(256, 2)
void gemm2_kernel(const float* __restrict__ W2l,
                  const float* __restrict__ b2l,
                  const float* __restrict__ W2r,
                  float* __restrict__ out) {
    __shared__ float As[BK][BM];
    __shared__ float Bs[BK][CLS];

    int t  = threadIdx.x;
    int m0 = blockIdx.x * BM;
    int tx = t & 15, ty = t >> 4;

    float acc[8][4];
#pragma unroll
    for (int i = 0; i < 8; i++)
#pragma unroll
        for (int j = 0; j < 4; j++) acc[i][j] = 0.f;

    int la_m = t >> 1;
    int la_k = (t & 1) * 8;
    int lb_n = t >> 2;                  // 0..63
    int lb_k = (t & 3) * 4;             // 0,4,8,12

    for (int kt = 0; kt < 256; kt += BK) {
        const float* Asrc = (kt < 128) ? g_agg : g_h;
        int ak = (kt < 128) ? kt : (kt - 128);
        int m  = m0 + la_m;
        float4 a0, a1;
        if (m < N_NODES) {
            const float4* ap = (const float4*)(Asrc + (size_t)m * FEAT + ak + la_k);
            a0 = __ldg(ap); a1 = __ldg(ap + 1);
        } else {
            a0 = make_float4(0.f, 0.f, 0.f, 0.f); a1 = a0;
        }
        const float* Wsrc = (kt < 128) ? W2l : W2r;
        float4 b0 = __ldg((const float4*)(Wsrc + lb_n * FEAT + ak + lb_k));

        __syncthreads();
        As[la_k + 0][la_m] = a0.x; As[la_k + 1][la_m] = a0.y;
        As[la_k + 2][la_m] = a0.z; As[la_k + 3][la_m] = a0.w;
        As[la_k + 4][la_m] = a1.x; As[la_k + 5][la_m] = a1.y;
        As[la_k + 6][la_m] = a1.z; As[la_k + 7][la_m] = a1.w;
        Bs[lb_k + 0][lb_n] = b0.x; Bs[lb_k + 1][lb_n] = b0.y;
        Bs[lb_k + 2][lb_n] = b0.z; Bs[lb_k + 3][lb_n] = b0.w;
        __syncthreads();

#pragma unroll
        for (int k = 0; k < BK; k++) {
            float a[8], b[4];
            *(float4*)(a)     = *(const float4*)&As[k][ty * 8];
            *(float4*)(a + 4) = *(const float4*)&As[k][ty * 8 + 4];
            *(float4*)(b)     = *(const float4*)&Bs[k][tx * 4];
#pragma unroll
            for (int i = 0; i < 8; i++)
#pragma unroll
                for (int j = 0; j < 4; j++)
                    acc[i][j] = fmaf(a[i], b[j], acc[i][j]);
        }
    }

    float bias[4];
    *(float4*)bias = __ldg((const float4*)(b2l + tx * 4));
#pragma unroll
    for (int i = 0; i < 8; i++)
#pragma unroll
        for (int j = 0; j < 4; j++) acc[i][j] += bias[j];

    // Row m = m0 + ty*8 + i is held by the 16 lanes sharing ty (contiguous
    // aligned 16-lane group inside a warp). Reduce with xor-shuffles.
#pragma unroll
    for (int i = 0; i < 8; i++) {
        float rmax = fmaxf(fmaxf(acc[i][0], acc[i][1]), fmaxf(acc[i][2], acc[i][3]));
#pragma unroll
        for (int off = 8; off > 0; off >>= 1)
            rmax = fmaxf(rmax, __shfl_xor_sync(0xffffffffu, rmax, off));
        float s = expf(acc[i][0] - rmax) + expf(acc[i][1] - rmax)
                + expf(acc[i][2] - rmax) + expf(acc[i][3] - rmax);
#pragma unroll
        for (int off = 8; off > 0; off >>= 1)
            s += __shfl_xor_sync(0xffffffffu, s, off);
        float lse = logf(s) + rmax;
        int m = m0 + ty * 8 + i;
        if (m < N_NODES) {
            float4 o;
            o.x = acc[i][0] - lse; o.y = acc[i][1] - lse;
            o.z = acc[i][2] - lse; o.w = acc[i][3] - lse;
            *(float4*)(out + (size_t)m * CLS + tx * 4) = o;
        }
    }
}

// ---------------------------------------------------------------------------
// Launch
// ---------------------------------------------------------------------------
extern "C" void kernel_launch(void* const* d_in, const int* in_sizes, int n_in,
                              void* d_out, int out_size) {
    const float* x    = (const float*)d_in[0];
    const int*   ei   = (const int*)d_in[1];
    const float* W1l  = (const float*)d_in[2];
    const float* b1l  = (const float*)d_in[3];
    const float* W1r  = (const float*)d_in[4];
    const float* W2l  = (const float*)d_in[5];
    const float* b2l  = (const float*)d_in[6];
    const float* W2r  = (const float*)d_in[7];
    float*       out  = (float*)d_out;

    const int n_edges = in_sizes[1] / 2;
    const int* srcs = ei;
    const int* dsts = ei + n_edges;

    const int scatter_blocks = (int)(((long long)n_edges * 32 + 255) / 256);
    const int scale_blocks   = (N_NODES * (FEAT / 4) + 255) / 256;
    const int gemm_blocks    = (N_NODES + BM - 1) / BM;

    // Layer 1
    zero_kernel<<<1024, 256>>>(1);
    scatter_kernel<<<scatter_blocks, 256>>>(x, srcs, dsts, n_edges, 1);
    scale_kernel<<<scale_blocks, 256>>>();
    gemm1_kernel<<<gemm_blocks, 256>>>(x, W1l, b1l, W1r);

    // Layer 2
    zero_kernel<<<1024, 256>>>(0);
    scatter_kernel<<<scatter_blocks, 256>>>(x, srcs, dsts, n_edges, 0);
    scale_kernel<<<scale_blocks, 256>>>();
    gemm2_kernel<<<gemm_blocks, 256>>>(W2l, b2l, W2r, out);
}

// round 3
// speedup vs baseline: 1.7327x; 1.7327x over previous
#include <cuda_runtime.h>

#define N_NODES 100000
#define FEAT    128
#define CLS     64

// Scratch (allocation-free rule: __device__ globals)
__device__ float g_agg[(size_t)N_NODES * FEAT];   // layer-1 aggregation accumulator
__device__ float g_h[(size_t)N_NODES * FEAT];     // layer-1 activations
__device__ float g_z[(size_t)N_NODES * CLS];      // h @ W2l^T (pre-aggregation)
__device__ float g_r[(size_t)N_NODES * CLS];      // h @ W2r^T (self term)
__device__ float g_zagg[(size_t)N_NODES * CLS];   // layer-2 aggregation accumulator
__device__ float g_cnt[N_NODES];                  // in-degree counts (float)

// ---------------------------------------------------------------------------
// Zero all accumulators + counts in one pass.
// ---------------------------------------------------------------------------
__global__ void zero_all_kernel() {
    int idx = blockIdx.x * blockDim.x + threadIdx.x;
    int stride = gridDim.x * blockDim.x;
    const int t_agg  = N_NODES * (FEAT / 4);
    const int t_zagg = N_NODES * (CLS / 4);
    float4 z = make_float4(0.f, 0.f, 0.f, 0.f);
    float4* pa = (float4*)g_agg;
    float4* pz = (float4*)g_zagg;
    for (int i = idx; i < t_agg; i += stride) pa[i] = z;
    for (int i = idx; i < t_zagg; i += stride) pz[i] = z;
    for (int i = idx; i < N_NODES; i += stride) g_cnt[i] = 0.f;
}

// ---------------------------------------------------------------------------
// Layer-1 edge scatter: one warp per edge, 128 floats. Also counts in-degree.
// ---------------------------------------------------------------------------
__global__ void scatter1_kernel(const float* __restrict__ x,
                                const int* __restrict__ srcs,
                                const int* __restrict__ dsts,
                                int n_edges) {
    int gt   = blockIdx.x * blockDim.x + threadIdx.x;
    int e    = gt >> 5;
    int lane = gt & 31;
    if (e >= n_edges) return;
    int s = __ldg(srcs + e);
    int d = __ldg(dsts + e);
    if ((unsigned)s >= N_NODES || (unsigned)d >= N_NODES) return;
    float4 v = __ldg((const float4*)(x + (size_t)s * FEAT) + lane);
    float* out = g_agg + (size_t)d * FEAT + lane * 4;
    asm volatile("red.global.add.v4.f32 [%0], {%1,%2,%3,%4};"
                 :: "l"(out), "f"(v.x), "f"(v.y), "f"(v.z), "f"(v.w)
                 : "memory");
    if (lane == 0) atomicAdd(g_cnt + d, 1.0f);
}

// ---------------------------------------------------------------------------
// Layer-2 edge scatter: 16 lanes per edge (2 edges/warp), 64 floats of g_z.
// ---------------------------------------------------------------------------
__global__ void scatter2_kernel(const int* __restrict__ srcs,
                                const int* __restrict__ dsts,
                                int n_edges) {
    int gt   = blockIdx.x * blockDim.x + threadIdx.x;
    int e    = gt >> 4;
    int lane = gt & 15;
    if (e >= n_edges) return;
    int s = __ldg(srcs + e);
    int d = __ldg(dsts + e);
    if ((unsigned)s >= N_NODES || (unsigned)d >= N_NODES) return;
    float4 v = __ldg((const float4*)(g_z + (size_t)s * CLS) + lane);
    float* out = g_zagg + (size_t)d * CLS + lane * 4;
    asm volatile("red.global.add.v4.f32 [%0], {%1,%2,%3,%4};"
                 :: "l"(out), "f"(v.x), "f"(v.y), "f"(v.z), "f"(v.w)
                 : "memory");
}

// ---------------------------------------------------------------------------
// GEMM1: h = relu([mean | x] @ [W1l; W1r]^T + b1l)
//   M = N_NODES, N = 128, K = 256 (concat). Mean-scale fused into A-load.
// ---------------------------------------------------------------------------
#define BM 128
#define BK 16

__global__ __launch_bounds__(256, 2)
void gemm1_kernel(const float* __restrict__ x,
                  const float* __restrict__ W1l,
                  const float* __restrict__ b1l,
                  const float* __restrict__ W1r) {
    __shared__ float As[BK][BM];
    __shared__ float Bs[BK][128];

    int t  = threadIdx.x;
    int m0 = blockIdx.x * BM;
    int tx = t & 15, ty = t >> 4;

    float acc[8][8];
#pragma unroll
    for (int i = 0; i < 8; i++)
#pragma unroll
        for (int j = 0; j < 8; j++) acc[i][j] = 0.f;

    int la_m = t >> 1;                  // 0..127
    int la_k = (t & 1) * 8;             // 0 or 8
    int lb_n = t >> 1;
    int lb_k = (t & 1) * 8;

    int m_load = m0 + la_m;
    float inv_m = 1.0f;
    if (m_load < N_NODES) inv_m = 1.0f / fmaxf(__ldg(g_cnt + m_load), 1.0f);

    for (int kt = 0; kt < 256; kt += BK) {
        const float* Asrc = (kt < 128) ? g_agg : x;
        float sc = (kt < 128) ? inv_m : 1.0f;
        int ak = (kt < 128) ? kt : (kt - 128);
        float4 a0, a1;
        if (m_load < N_NODES) {
            const float4* ap = (const float4*)(Asrc + (size_t)m_load * FEAT + ak + la_k);
            a0 = __ldg(ap); a1 = __ldg(ap + 1);
            a0.x *= sc; a0.y *= sc; a0.z *= sc; a0.w *= sc;
            a1.x *= sc; a1.y *= sc; a1.z *= sc; a1.w *= sc;
        } else {
            a0 = make_float4(0.f, 0.f, 0.f, 0.f); a1 = a0;
        }
        const float* Wsrc = (kt < 128) ? W1l : W1r;
        const float4* bp = (const float4*)(Wsrc + lb_n * FEAT + ak + lb_k);
        float4 b0 = __ldg(bp), b1 = __ldg(bp + 1);

        __syncthreads();
        As[la_k + 0][la_m] = a0.x; As[la_k + 1][la_m] = a0.y;
        As[la_k + 2][la_m] = a0.z; As[la_k + 3][la_m] = a0.w;
        As[la_k + 4][la_m] = a1.x; As[la_k + 5][la_m] = a1.y;
        As[la_k + 6][la_m] = a1.z; As[la_k + 7][la_m] = a1.w;
        Bs[lb_k + 0][lb_n] = b0.x; Bs[lb_k + 1][lb_n] = b0.y;
        Bs[lb_k + 2][lb_n] = b0.z; Bs[lb_k + 3][lb_n] = b0.w;
        Bs[lb_k + 4][lb_n] = b1.x; Bs[lb_k + 5][lb_n] = b1.y;
        Bs[lb_k + 6][lb_n] = b1.z; Bs[lb_k + 7][lb_n] = b1.w;
        __syncthreads();

#pragma unroll
        for (int k = 0; k < BK; k++) {
            float a[8], b[8];
            *(float4*)(a)     = *(const float4*)&As[k][ty * 8];
            *(float4*)(a + 4) = *(const float4*)&As[k][ty * 8 + 4];
            *(float4*)(b)     = *(const float4*)&Bs[k][tx * 8];
            *(float4*)(b + 4) = *(const float4*)&Bs[k][tx * 8 + 4];
#pragma unroll
            for (int i = 0; i < 8; i++)
#pragma unroll
                for (int j = 0; j < 8; j++)
                    acc[i][j] = fmaf(a[i], b[j], acc[i][j]);
        }
    }

    float bias[8];
    *(float4*)(bias)     = __ldg((const float4*)(b1l + tx * 8));
    *(float4*)(bias + 4) = __ldg((const float4*)(b1l + tx * 8 + 4));

#pragma unroll
    for (int i = 0; i < 8; i++) {
        int m = m0 + ty * 8 + i;
        if (m < N_NODES) {
            float4 o0, o1;
            o0.x = fmaxf(acc[i][0] + bias[0], 0.f);
            o0.y = fmaxf(acc[i][1] + bias[1], 0.f);
            o0.z = fmaxf(acc[i][2] + bias[2], 0.f);
            o0.w = fmaxf(acc[i][3] + bias[3], 0.f);
            o1.x = fmaxf(acc[i][4] + bias[4], 0.f);
            o1.y = fmaxf(acc[i][5] + bias[5], 0.f);
            o1.z = fmaxf(acc[i][6] + bias[6], 0.f);
            o1.w = fmaxf(acc[i][7] + bias[7], 0.f);
            float4* hp = (float4*)(g_h + (size_t)m * FEAT + tx * 8);
            hp[0] = o0; hp[1] = o1;
        }
    }
}

// ---------------------------------------------------------------------------
// GEMM2: y = h @ [W2l; W2r]^T  (M = N_NODES, N = 128, K = 128)
//   First 64 output cols -> g_z (to be aggregated), last 64 -> g_r (self).
// ---------------------------------------------------------------------------
__global__ __launch_bounds__(256, 2)
void gemm2_kernel(const float* __restrict__ W2l,
                  const float* __restrict__ W2r) {
    __shared__ float As[BK][BM];
    __shared__ float Bs[BK][128];

    int t  = threadIdx.x;
    int m0 = blockIdx.x * BM;
    int tx = t & 15, ty = t >> 4;

    float acc[8][8];
#pragma unroll
    for (int i = 0; i < 8; i++)
#pragma unroll
        for (int j = 0; j < 8; j++) acc[i][j] = 0.f;

    int la_m = t >> 1;
    int la_k = (t & 1) * 8;
    int lb_n = t >> 1;                  // output col 0..127
    int lb_k = (t & 1) * 8;

    int m_load = m0 + la_m;
    const float* Wrow = (lb_n < 64) ? (W2l + lb_n * FEAT)
                                    : (W2r + (lb_n - 64) * FEAT);

    for (int kt = 0; kt < 128; kt += BK) {
        float4 a0, a1;
        if (m_load < N_NODES) {
            const float4* ap = (const float4*)(g_h + (size_t)m_load * FEAT + kt + la_k);
            a0 = __ldg(ap); a1 = __ldg(ap + 1);
        } else {
            a0 = make_float4(0.f, 0.f, 0.f, 0.f); a1 = a0;
        }
        const float4* bp = (const float4*)(Wrow + kt + lb_k);
        float4 b0 = __ldg(bp), b1 = __ldg(bp + 1);

        __syncthreads();
        As[la_k + 0][la_m] = a0.x; As[la_k + 1][la_m] = a0.y;
        As[la_k + 2][la_m] = a0.z; As[la_k + 3][la_m] = a0.w;
        As[la_k + 4][la_m] = a1.x; As[la_k + 5][la_m] = a1.y;
        As[la_k + 6][la_m] = a1.z; As[la_k + 7][la_m] = a1.w;
        Bs[lb_k + 0][lb_n] = b0.x; Bs[lb_k + 1][lb_n] = b0.y;
        Bs[lb_k + 2][lb_n] = b0.z; Bs[lb_k + 3][lb_n] = b0.w;
        Bs[lb_k + 4][lb_n] = b1.x; Bs[lb_k + 5][lb_n] = b1.y;
        Bs[lb_k + 6][lb_n] = b1.z; Bs[lb_k + 7][lb_n] = b1.w;
        __syncthreads();

#pragma unroll
        for (int k = 0; k < BK; k++) {
            float a[8], b[8];
            *(float4*)(a)     = *(const float4*)&As[k][ty * 8];
            *(float4*)(a + 4) = *(const float4*)&As[k][ty * 8 + 4];
            *(float4*)(b)     = *(const float4*)&Bs[k][tx * 8];
            *(float4*)(b + 4) = *(const float4*)&Bs[k][tx * 8 + 4];
#pragma unroll
            for (int i = 0; i < 8; i++)
#pragma unroll
                for (int j = 0; j < 8; j++)
                    acc[i][j] = fmaf(a[i], b[j], acc[i][j]);
        }
    }

    // cols tx*8..tx*8+7: tx<8 -> g_z col tx*8, tx>=8 -> g_r col tx*8-64
    float* dstbase = (tx < 8) ? g_z : g_r;
    int col = (tx < 8) ? tx * 8 : tx * 8 - 64;
#pragma unroll
    for (int i = 0; i < 8; i++) {
        int m = m0 + ty * 8 + i;
        if (m < N_NODES) {
            float4 o0 = make_float4(acc[i][0], acc[i][1], acc[i][2], acc[i][3]);
            float4 o1 = make_float4(acc[i][4], acc[i][5], acc[i][6], acc[i][7]);
            float4* p = (float4*)(dstbase + (size_t)m * CLS + col);
            p[0] = o0; p[1] = o1;
        }
    }
}

// ---------------------------------------------------------------------------
// Final: out = log_softmax(zagg/cnt + b2l + r). 16 lanes per node.
// ---------------------------------------------------------------------------
__global__ void final_kernel(const float* __restrict__ b2l,
                             float* __restrict__ out) {
    int gt   = blockIdx.x * blockDim.x + threadIdx.x;
    int m    = gt >> 4;
    int lane = gt & 15;
    if (m >= N_NODES) return;

    float inv = 1.0f / fmaxf(__ldg(g_cnt + m), 1.0f);
    float4 za = *(const float4*)(g_zagg + (size_t)m * CLS + lane * 4);
    float4 r  = *(const float4*)(g_r   + (size_t)m * CLS + lane * 4);
    float4 bb = __ldg((const float4*)(b2l + lane * 4));

    float v[4];
    v[0] = za.x * inv + bb.x + r.x;
    v[1] = za.y * inv + bb.y + r.y;
    v[2] = za.z * inv + bb.z + r.z;
    v[3] = za.w * inv + bb.w + r.w;

    float rmax = fmaxf(fmaxf(v[0], v[1]), fmaxf(v[2], v[3]));
#pragma unroll
    for (int off = 8; off > 0; off >>= 1)
        rmax = fmaxf(rmax, __shfl_xor_sync(0xffffffffu, rmax, off));
    float s = expf(v[0] - rmax) + expf(v[1] - rmax)
            + expf(v[2] - rmax) + expf(v[3] - rmax);
#pragma unroll
    for (int off = 8; off > 0; off >>= 1)
        s += __shfl_xor_sync(0xffffffffu, s, off);
    float lse = logf(s) + rmax;

    float4 o;
    o.x = v[0] - lse; o.y = v[1] - lse; o.z = v[2] - lse; o.w = v[3] - lse;
    *(float4*)(out + (size_t)m * CLS + lane * 4) = o;
}

// ---------------------------------------------------------------------------
// Launch
// ---------------------------------------------------------------------------
extern "C" void kernel_launch(void* const* d_in, const int* in_sizes, int n_in,
                              void* d_out, int out_size) {
    const float* x    = (const float*)d_in[0];
    const int*   ei   = (const int*)d_in[1];
    const float* W1l  = (const float*)d_in[2];
    const float* b1l  = (const float*)d_in[3];
    const float* W1r  = (const float*)d_in[4];
    const float* W2l  = (const float*)d_in[5];
    const float* b2l  = (const float*)d_in[6];
    const float* W2r  = (const float*)d_in[7];
    float*       out  = (float*)d_out;

    const int n_edges = in_sizes[1] / 2;
    const int* srcs = ei;
    const int* dsts = ei + n_edges;

    const int sc1_blocks = (int)(((long long)n_edges * 32 + 255) / 256);
    const int sc2_blocks = (int)(((long long)n_edges * 16 + 255) / 256);
    const int gemm_blocks = (N_NODES + BM - 1) / BM;
    const int fin_blocks  = (N_NODES * 16 + 255) / 256;

    zero_all_kernel<<<1024, 256>>>();
    scatter1_kernel<<<sc1_blocks, 256>>>(x, srcs, dsts, n_edges);
    gemm1_kernel<<<gemm_blocks, 256>>>(x, W1l, b1l, W1r);
    gemm2_kernel<<<gemm_blocks, 256>>>(W2l, W2r);
    scatter2_kernel<<<sc2_blocks, 256>>>(srcs, dsts, n_edges);
    final_kernel<<<fin_blocks, 256>>>(b2l, out);
}

// round 4
// speedup vs baseline: 2.2822x; 1.3172x over previous
#include <cuda_runtime.h>

#define N_NODES 100000
#define FEAT    128
#define CLS     64

// Scratch (allocation-free rule: __device__ globals)
__device__ float g_agg[(size_t)N_NODES * FEAT];   // layer-1 aggregation accumulator
__device__ float g_h[(size_t)N_NODES * FEAT];     // layer-1 activations
__device__ float g_z[(size_t)N_NODES * CLS];      // h @ W2l^T (pre-aggregation)
__device__ float g_r[(size_t)N_NODES * CLS];      // h @ W2r^T (self term)
__device__ float g_zagg[(size_t)N_NODES * CLS];   // layer-2 aggregation accumulator
__device__ float g_cnt[N_NODES];                  // in-degree counts (float)

// ---------------------------------------------------------------------------
__global__ void zero_all_kernel() {
    int idx = blockIdx.x * blockDim.x + threadIdx.x;
    int stride = gridDim.x * blockDim.x;
    const int t_agg  = N_NODES * (FEAT / 4);
    const int t_zagg = N_NODES * (CLS / 4);
    float4 z = make_float4(0.f, 0.f, 0.f, 0.f);
    float4* pa = (float4*)g_agg;
    float4* pz = (float4*)g_zagg;
    for (int i = idx; i < t_agg; i += stride) pa[i] = z;
    for (int i = idx; i < t_zagg; i += stride) pz[i] = z;
    for (int i = idx; i < N_NODES; i += stride) g_cnt[i] = 0.f;
}

// ---------------------------------------------------------------------------
// Layer-1 edge scatter: one warp per edge, 128 floats + in-degree count.
// ---------------------------------------------------------------------------
__global__ void scatter1_kernel(const float* __restrict__ x,
                                const int* __restrict__ srcs,
                                const int* __restrict__ dsts,
                                int n_edges) {
    int gt   = blockIdx.x * blockDim.x + threadIdx.x;
    int e    = gt >> 5;
    int lane = gt & 31;
    if (e >= n_edges) return;
    int s = __ldg(srcs + e);
    int d = __ldg(dsts + e);
    if ((unsigned)s >= N_NODES || (unsigned)d >= N_NODES) return;
    float4 v = __ldg((const float4*)(x + (size_t)s * FEAT) + lane);
    float* out = g_agg + (size_t)d * FEAT + lane * 4;
    asm volatile("red.global.add.v4.f32 [%0], {%1,%2,%3,%4};"
                 :: "l"(out), "f"(v.x), "f"(v.y), "f"(v.z), "f"(v.w)
                 : "memory");
    if (lane == 0) atomicAdd(g_cnt + d, 1.0f);
}

// ---------------------------------------------------------------------------
// Layer-2 edge scatter: 16 lanes per edge, 64 floats of g_z.
// ---------------------------------------------------------------------------
__global__ void scatter2_kernel(const int* __restrict__ srcs,
                                const int* __restrict__ dsts,
                                int n_edges) {
    int gt   = blockIdx.x * blockDim.x + threadIdx.x;
    int e    = gt >> 4;
    int lane = gt & 15;
    if (e >= n_edges) return;
    int s = __ldg(srcs + e);
    int d = __ldg(dsts + e);
    if ((unsigned)s >= N_NODES || (unsigned)d >= N_NODES) return;
    float4 v = __ldg((const float4*)(g_z + (size_t)s * CLS) + lane);
    float* out = g_zagg + (size_t)d * CLS + lane * 4;
    asm volatile("red.global.add.v4.f32 [%0], {%1,%2,%3,%4};"
                 :: "l"(out), "f"(v.x), "f"(v.y), "f"(v.z), "f"(v.w)
                 : "memory");
}

// ---------------------------------------------------------------------------
// TF32 tensor-core GEMM infrastructure
//   Block tile 128x128, 8 warps, warp tile 32x64 (2 x 8 m16n8k8 tiles), BK=16.
//   smem rows padded to stride 20 floats -> conflict-free fragment loads.
// ---------------------------------------------------------------------------
#define SMSTRIDE 20

__device__ __forceinline__ unsigned f2tf32(float f) {
    unsigned u;
    asm("cvt.rna.tf32.f32 %0, %1;" : "=r"(u) : "f"(f));
    return u;
}

#define MMA_TF32(c, a, b)                                                     \
    asm volatile("mma.sync.aligned.m16n8k8.row.col.f32.tf32.tf32.f32 "        \
                 "{%0,%1,%2,%3}, {%4,%5,%6,%7}, {%8,%9}, {%0,%1,%2,%3};"      \
                 : "+f"((c)[0]), "+f"((c)[1]), "+f"((c)[2]), "+f"((c)[3])     \
                 : "r"((a)[0]), "r"((a)[1]), "r"((a)[2]), "r"((a)[3]),        \
                   "r"((b)[0]), "r"((b)[1]))

// ---------------------------------------------------------------------------
// GEMM1: h = relu([mean | x] @ [W1l; W1r]^T + b1l), K = 256 (concat).
// Mean-scale fused into A-load.
// ---------------------------------------------------------------------------
__global__ __launch_bounds__(256, 2)
void gemm1_tc(const float* __restrict__ x,
              const float* __restrict__ W1l,
              const float* __restrict__ b1l,
              const float* __restrict__ W1r) {
    __shared__ unsigned As[128 * SMSTRIDE];
    __shared__ unsigned Bs[128 * SMSTRIDE];

    int t    = threadIdx.x;
    int lane = t & 31, w = t >> 5;
    int g    = lane >> 2, tig = lane & 3;
    int wm   = w & 3, wn = w >> 2;          // 4 M-warps x 2 N-warps
    int m0   = blockIdx.x * 128;

    float acc[2][8][4];
#pragma unroll
    for (int mt = 0; mt < 2; mt++)
#pragma unroll
        for (int nt = 0; nt < 8; nt++)
#pragma unroll
            for (int i = 0; i < 4; i++) acc[mt][nt][i] = 0.f;

    int lrow = t >> 1;                       // 0..127 (A row within tile / B out-col)
    int lk   = (t & 1) * 8;                  // 0 or 8
    int arow = m0 + lrow;
    bool valid = arow < N_NODES;
    float inv_m = 1.0f;
    if (valid) inv_m = 1.0f / fmaxf(__ldg(g_cnt + arow), 1.0f);

    unsigned stA[8], stB[8];

    // ---- tile loader (kt in [0,256), step 16) ----
    auto load_tile = [&](int kt) {
        const float* Asrc = (kt < 128) ? g_agg : x;
        float sc = (kt < 128) ? inv_m : 1.0f;
        int ak = (kt < 128) ? kt : (kt - 128);
        float4 a0, a1;
        if (valid) {
            const float4* ap = (const float4*)(Asrc + (size_t)arow * FEAT + ak + lk);
            a0 = __ldg(ap); a1 = __ldg(ap + 1);
        } else {
            a0 = make_float4(0.f, 0.f, 0.f, 0.f); a1 = a0;
        }
        stA[0] = f2tf32(a0.x * sc); stA[1] = f2tf32(a0.y * sc);
        stA[2] = f2tf32(a0.z * sc); stA[3] = f2tf32(a0.w * sc);
        stA[4] = f2tf32(a1.x * sc); stA[5] = f2tf32(a1.y * sc);
        stA[6] = f2tf32(a1.z * sc); stA[7] = f2tf32(a1.w * sc);

        const float* Wsrc = (kt < 128) ? W1l : W1r;
        const float4* bp = (const float4*)(Wsrc + (size_t)lrow * FEAT + ak + lk);
        float4 b0 = __ldg(bp), b1 = __ldg(bp + 1);
        stB[0] = f2tf32(b0.x); stB[1] = f2tf32(b0.y);
        stB[2] = f2tf32(b0.z); stB[3] = f2tf32(b0.w);
        stB[4] = f2tf32(b1.x); stB[5] = f2tf32(b1.y);
        stB[6] = f2tf32(b1.z); stB[7] = f2tf32(b1.w);
    };

    load_tile(0);

    for (int kt = 0; kt < 256; kt += 16) {
        __syncthreads();
        {
            unsigned* pa = &As[lrow * SMSTRIDE + lk];
            *(uint4*)pa       = make_uint4(stA[0], stA[1], stA[2], stA[3]);
            *(uint4*)(pa + 4) = make_uint4(stA[4], stA[5], stA[6], stA[7]);
            unsigned* pb = &Bs[lrow * SMSTRIDE + lk];
            *(uint4*)pb       = make_uint4(stB[0], stB[1], stB[2], stB[3]);
            *(uint4*)(pb + 4) = make_uint4(stB[4], stB[5], stB[6], stB[7]);
        }
        __syncthreads();
        if (kt + 16 < 256) load_tile(kt + 16);

#pragma unroll
        for (int ks = 0; ks < 2; ks++) {
            int k0 = ks * 8;
            unsigned afr[2][4], bfr[8][2];
#pragma unroll
            for (int mt = 0; mt < 2; mt++) {
                int r = wm * 32 + mt * 16 + g;
                afr[mt][0] = As[r * SMSTRIDE + k0 + tig];
                afr[mt][1] = As[(r + 8) * SMSTRIDE + k0 + tig];
                afr[mt][2] = As[r * SMSTRIDE + k0 + tig + 4];
                afr[mt][3] = As[(r + 8) * SMSTRIDE + k0 + tig + 4];
            }
#pragma unroll
            for (int nt = 0; nt < 8; nt++) {
                int c = wn * 64 + nt * 8 + g;
                bfr[nt][0] = Bs[c * SMSTRIDE + k0 + tig];
                bfr[nt][1] = Bs[c * SMSTRIDE + k0 + tig + 4];
            }
#pragma unroll
            for (int mt = 0; mt < 2; mt++)
#pragma unroll
                for (int nt = 0; nt < 8; nt++)
                    MMA_TF32(acc[mt][nt], afr[mt], bfr[nt]);
        }
    }

    // Epilogue: bias + relu -> g_h
#pragma unroll
    for (int nt = 0; nt < 8; nt++) {
        int col = wn * 64 + nt * 8 + 2 * tig;
        float2 bias = __ldg((const float2*)(b1l + col));
#pragma unroll
        for (int mt = 0; mt < 2; mt++) {
            int r = m0 + wm * 32 + mt * 16 + g;
            if (r < N_NODES) {
                float2 o;
                o.x = fmaxf(acc[mt][nt][0] + bias.x, 0.f);
                o.y = fmaxf(acc[mt][nt][1] + bias.y, 0.f);
                *(float2*)(g_h + (size_t)r * FEAT + col) = o;
            }
            if (r + 8 < N_NODES) {
                float2 o;
                o.x = fmaxf(acc[mt][nt][2] + bias.x, 0.f);
                o.y = fmaxf(acc[mt][nt][3] + bias.y, 0.f);
                *(float2*)(g_h + (size_t)(r + 8) * FEAT + col) = o;
            }
        }
    }
}

// ---------------------------------------------------------------------------
// GEMM2: y = h @ [W2l; W2r]^T  (K = 128). Cols <64 -> g_z, >=64 -> g_r.
// ---------------------------------------------------------------------------
__global__ __launch_bounds__(256, 2)
void gemm2_tc(const float* __restrict__ W2l,
              const float* __restrict__ W2r) {
    __shared__ unsigned As[128 * SMSTRIDE];
    __shared__ unsigned Bs[128 * SMSTRIDE];

    int t    = threadIdx.x;
    int lane = t & 31, w = t >> 5;
    int g    = lane >> 2, tig = lane & 3;
    int wm   = w & 3, wn = w >> 2;
    int m0   = blockIdx.x * 128;

    float acc[2][8][4];
#pragma unroll
    for (int mt = 0; mt < 2; mt++)
#pragma unroll
        for (int nt = 0; nt < 8; nt++)
#pragma unroll
            for (int i = 0; i < 4; i++) acc[mt][nt][i] = 0.f;

    int lrow = t >> 1;
    int lk   = (t & 1) * 8;
    int arow = m0 + lrow;
    bool valid = arow < N_NODES;
    const float* Wrow = (lrow < 64) ? (W2l + (size_t)lrow * FEAT)
                                    : (W2r + (size_t)(lrow - 64) * FEAT);

    unsigned stA[8], stB[8];

    auto load_tile = [&](int kt) {
        float4 a0, a1;
        if (valid) {
            const float4* ap = (const float4*)(g_h + (size_t)arow * FEAT + kt + lk);
            a0 = __ldg(ap); a1 = __ldg(ap + 1);
        } else {
            a0 = make_float4(0.f, 0.f, 0.f, 0.f); a1 = a0;
        }
        stA[0] = f2tf32(a0.x); stA[1] = f2tf32(a0.y);
        stA[2] = f2tf32(a0.z); stA[3] = f2tf32(a0.w);
        stA[4] = f2tf32(a1.x); stA[5] = f2tf32(a1.y);
        stA[6] = f2tf32(a1.z); stA[7] = f2tf32(a1.w);

        const float4* bp = (const float4*)(Wrow + kt + lk);
        float4 b0 = __ldg(bp), b1 = __ldg(bp + 1);
        stB[0] = f2tf32(b0.x); stB[1] = f2tf32(b0.y);
        stB[2] = f2tf32(b0.z); stB[3] = f2tf32(b0.w);
        stB[4] = f2tf32(b1.x); stB[5] = f2tf32(b1.y);
        stB[6] = f2tf32(b1.z); stB[7] = f2tf32(b1.w);
    };

    load_tile(0);

    for (int kt = 0; kt < 128; kt += 16) {
        __syncthreads();
        {
            unsigned* pa = &As[lrow * SMSTRIDE + lk];
            *(uint4*)pa       = make_uint4(stA[0], stA[1], stA[2], stA[3]);
            *(uint4*)(pa + 4) = make_uint4(stA[4], stA[5], stA[6], stA[7]);
            unsigned* pb = &Bs[lrow * SMSTRIDE + lk];
            *(uint4*)pb       = make_uint4(stB[0], stB[1], stB[2], stB[3]);
            *(uint4*)(pb + 4) = make_uint4(stB[4], stB[5], stB[6], stB[7]);
        }
        __syncthreads();
        if (kt + 16 < 128) load_tile(kt + 16);

#pragma unroll
        for (int ks = 0; ks < 2; ks++) {
            int k0 = ks * 8;
            unsigned afr[2][4], bfr[8][2];
#pragma unroll
            for (int mt = 0; mt < 2; mt++) {
                int r = wm * 32 + mt * 16 + g;
                afr[mt][0] = As[r * SMSTRIDE + k0 + tig];
                afr[mt][1] = As[(r + 8) * SMSTRIDE + k0 + tig];
                afr[mt][2] = As[r * SMSTRIDE + k0 + tig + 4];
                afr[mt][3] = As[(r + 8) * SMSTRIDE + k0 + tig + 4];
            }
#pragma unroll
            for (int nt = 0; nt < 8; nt++) {
                int c = wn * 64 + nt * 8 + g;
                bfr[nt][0] = Bs[c * SMSTRIDE + k0 + tig];
                bfr[nt][1] = Bs[c * SMSTRIDE + k0 + tig + 4];
            }
#pragma unroll
            for (int mt = 0; mt < 2; mt++)
#pragma unroll
                for (int nt = 0; nt < 8; nt++)
                    MMA_TF32(acc[mt][nt], afr[mt], bfr[nt]);
        }
    }

    // Epilogue: split to g_z / g_r
#pragma unroll
    for (int nt = 0; nt < 8; nt++) {
        int col = wn * 64 + nt * 8 + 2 * tig;
        float* dst = (col < 64) ? g_z : g_r;
        int c2 = (col < 64) ? col : col - 64;
#pragma unroll
        for (int mt = 0; mt < 2; mt++) {
            int r = m0 + wm * 32 + mt * 16 + g;
            if (r < N_NODES) {
                float2 o = make_float2(acc[mt][nt][0], acc[mt][nt][1]);
                *(float2*)(dst + (size_t)r * CLS + c2) = o;
            }
            if (r + 8 < N_NODES) {
                float2 o = make_float2(acc[mt][nt][2], acc[mt][nt][3]);
                *(float2*)(dst + (size_t)(r + 8) * CLS + c2) = o;
            }
        }
    }
}

// ---------------------------------------------------------------------------
// Final: out = log_softmax(zagg/cnt + b2l + r). 16 lanes per node.
// ---------------------------------------------------------------------------
__global__ void final_kernel(const float* __restrict__ b2l,
                             float* __restrict__ out) {
    int gt   = blockIdx.x * blockDim.x + threadIdx.x;
    int m    = gt >> 4;
    int lane = gt & 15;
    if (m >= N_NODES) return;

    float inv = 1.0f / fmaxf(__ldg(g_cnt + m), 1.0f);
    float4 za = *(const float4*)(g_zagg + (size_t)m * CLS + lane * 4);
    float4 r  = *(const float4*)(g_r   + (size_t)m * CLS + lane * 4);
    float4 bb = __ldg((const float4*)(b2l + lane * 4));

    float v[4];
    v[0] = za.x * inv + bb.x + r.x;
    v[1] = za.y * inv + bb.y + r.y;
    v[2] = za.z * inv + bb.z + r.z;
    v[3] = za.w * inv + bb.w + r.w;

    float rmax = fmaxf(fmaxf(v[0], v[1]), fmaxf(v[2], v[3]));
#pragma unroll
    for (int off = 8; off > 0; off >>= 1)
        rmax = fmaxf(rmax, __shfl_xor_sync(0xffffffffu, rmax, off));
    float s = expf(v[0] - rmax) + expf(v[1] - rmax)
            + expf(v[2] - rmax) + expf(v[3] - rmax);
#pragma unroll
    for (int off = 8; off > 0; off >>= 1)
        s += __shfl_xor_sync(0xffffffffu, s, off);
    float lse = logf(s) + rmax;

    float4 o;
    o.x = v[0] - lse; o.y = v[1] - lse; o.z = v[2] - lse; o.w = v[3] - lse;
    *(float4*)(out + (size_t)m * CLS + lane * 4) = o;
}

// ---------------------------------------------------------------------------
// Launch
// ---------------------------------------------------------------------------
extern "C" void kernel_launch(void* const* d_in, const int* in_sizes, int n_in,
                              void* d_out, int out_size) {
    const float* x    = (const float*)d_in[0];
    const int*   ei   = (const int*)d_in[1];
    const float* W1l  = (const float*)d_in[2];
    const float* b1l  = (const float*)d_in[3];
    const float* W1r  = (const float*)d_in[4];
    const float* W2l  = (const float*)d_in[5];
    const float* b2l  = (const float*)d_in[6];
    const float* W2r  = (const float*)d_in[7];
    float*       out  = (float*)d_out;

    const int n_edges = in_sizes[1] / 2;
    const int* srcs = ei;
    const int* dsts = ei + n_edges;

    const int sc1_blocks = (int)(((long long)n_edges * 32 + 255) / 256);
    const int sc2_blocks = (int)(((long long)n_edges * 16 + 255) / 256);
    const int gemm_blocks = (N_NODES + 127) / 128;
    const int fin_blocks  = (N_NODES * 16 + 255) / 256;

    zero_all_kernel<<<1024, 256>>>();
    scatter1_kernel<<<sc1_blocks, 256>>>(x, srcs, dsts, n_edges);
    gemm1_tc<<<gemm_blocks, 256>>>(x, W1l, b1l, W1r);
    gemm2_tc<<<gemm_blocks, 256>>>(W2l, W2r);
    scatter2_kernel<<<sc2_blocks, 256>>>(srcs, dsts, n_edges);
    final_kernel<<<fin_blocks, 256>>>(b2l, out);
}

// round 5
// speedup vs baseline: 2.8250x; 1.2378x over previous
#include <cuda_runtime.h>

#define N_NODES 100000
#define FEAT    128
#define CLS     64
#define MAX_EDGES 1700000

// Scratch (allocation-free rule: __device__ globals)
__device__ float g_agg[(size_t)N_NODES * FEAT];   // layer-1 mean aggregation
__device__ float g_h[(size_t)N_NODES * FEAT];     // layer-1 activations
__device__ float g_z[(size_t)N_NODES * CLS];      // h @ W2l^T (pre-aggregation)
__device__ float g_r[(size_t)N_NODES * CLS];      // h @ W2r^T (self term)
__device__ float g_zagg[(size_t)N_NODES * CLS];   // layer-2 mean aggregation
// CSR machinery
__device__ int g_hist[N_NODES];
__device__ int g_row_ptr[N_NODES + 1];
__device__ int g_cursor[N_NODES];
__device__ int g_col[MAX_EDGES];
__device__ int g_part[256];        // per-block partial sums for scan
__device__ int g_part_scan[256];   // exclusive-scanned partials
__device__ int g_total;

#define SCAN_BLOCKS 200
#define SCAN_CHUNK  512            // SCAN_BLOCKS*SCAN_CHUNK = 102400 >= N_NODES

// ---------------------------------------------------------------------------
// CSR build
// ---------------------------------------------------------------------------
__global__ void zero_hist_kernel() {
    int i = blockIdx.x * blockDim.x + threadIdx.x;
    if (i < N_NODES) g_hist[i] = 0;
}

__global__ void hist_kernel(const int* __restrict__ srcs,
                            const int* __restrict__ dsts, int n_edges) {
    int e = blockIdx.x * blockDim.x + threadIdx.x;
    if (e >= n_edges) return;
    int s = __ldg(srcs + e);
    int d = __ldg(dsts + e);
    if ((unsigned)s >= N_NODES || (unsigned)d >= N_NODES) return;
    atomicAdd(g_hist + d, 1);
}

__global__ void scan_a_kernel() {                 // block partial sums
    __shared__ int sm[256];
    int b = blockIdx.x, t = threadIdx.x;
    int i0 = b * SCAN_CHUNK + t;
    int i1 = i0 + 256;
    int v = 0;
    if (i0 < N_NODES) v += g_hist[i0];
    if (i1 < N_NODES) v += g_hist[i1];
    sm[t] = v;
    __syncthreads();
#pragma unroll
    for (int off = 128; off > 0; off >>= 1) {
        if (t < off) sm[t] += sm[t + off];
        __syncthreads();
    }
    if (t == 0) g_part[b] = sm[0];
}

__global__ void scan_b_kernel() {                 // scan the 200 partials
    __shared__ int sm[256];
    int t = threadIdx.x;
    int v = (t < SCAN_BLOCKS) ? g_part[t] : 0;
    sm[t] = v;
    __syncthreads();
#pragma unroll
    for (int off = 1; off < 256; off <<= 1) {
        int add = (t >= off) ? sm[t - off] : 0;
        __syncthreads();
        sm[t] += add;
        __syncthreads();
    }
    if (t < SCAN_BLOCKS) g_part_scan[t] = sm[t] - v;   // exclusive
    if (t == 0) g_total = sm[255];
}

__global__ void scan_c_kernel() {                 // per-chunk exclusive scan
    __shared__ int sm[256];
    int b = blockIdx.x, t = threadIdx.x;
    int base = b * SCAN_CHUNK + 2 * t;            // 2 consecutive elems/thread
    int a0 = (base     < N_NODES) ? g_hist[base]     : 0;
    int a1 = (base + 1 < N_NODES) ? g_hist[base + 1] : 0;
    int s = a0 + a1;
    sm[t] = s;
    __syncthreads();
#pragma unroll
    for (int off = 1; off < 256; off <<= 1) {
        int add = (t >= off) ? sm[t - off] : 0;
        __syncthreads();
        sm[t] += add;
        __syncthreads();
    }
    int offset = g_part_scan[b] + sm[t] - s;      // exclusive within chunk + block base
    if (base < N_NODES) {
        g_row_ptr[base] = offset;
        g_cursor[base]  = offset;
    }
    if (base + 1 < N_NODES) {
        g_row_ptr[base + 1] = offset + a0;
        g_cursor[base + 1]  = offset + a0;
    }
    if (b == 0 && t == 0) g_row_ptr[N_NODES] = g_total;
}

__global__ void fill_kernel(const int* __restrict__ srcs,
                            const int* __restrict__ dsts, int n_edges) {
    int e = blockIdx.x * blockDim.x + threadIdx.x;
    if (e >= n_edges) return;
    int s = __ldg(srcs + e);
    int d = __ldg(dsts + e);
    if ((unsigned)s >= N_NODES || (unsigned)d >= N_NODES) return;
    int pos = atomicAdd(g_cursor + d, 1);
    g_col[pos] = s;
}

// ---------------------------------------------------------------------------
// Aggregate layer 1: warp per node, mean of x[src] rows -> g_agg (mean folded).
// ---------------------------------------------------------------------------
__global__ void aggregate1_kernel(const float* __restrict__ x) {
    int wid  = (blockIdx.x * blockDim.x + threadIdx.x) >> 5;
    int lane = threadIdx.x & 31;
    if (wid >= N_NODES) return;
    int beg = __ldg(g_row_ptr + wid), end = __ldg(g_row_ptr + wid + 1);

    float4 acc = make_float4(0.f, 0.f, 0.f, 0.f);
    int i = beg;
    for (; i + 4 <= end; i += 4) {
        int s0 = __ldg(g_col + i),     s1 = __ldg(g_col + i + 1);
        int s2 = __ldg(g_col + i + 2), s3 = __ldg(g_col + i + 3);
        float4 v0 = __ldg((const float4*)(x + (size_t)s0 * FEAT) + lane);
        float4 v1 = __ldg((const float4*)(x + (size_t)s1 * FEAT) + lane);
        float4 v2 = __ldg((const float4*)(x + (size_t)s2 * FEAT) + lane);
        float4 v3 = __ldg((const float4*)(x + (size_t)s3 * FEAT) + lane);
        acc.x += v0.x + v1.x + v2.x + v3.x;
        acc.y += v0.y + v1.y + v2.y + v3.y;
        acc.z += v0.z + v1.z + v2.z + v3.z;
        acc.w += v0.w + v1.w + v2.w + v3.w;
    }
    for (; i < end; i++) {
        int s = __ldg(g_col + i);
        float4 v = __ldg((const float4*)(x + (size_t)s * FEAT) + lane);
        acc.x += v.x; acc.y += v.y; acc.z += v.z; acc.w += v.w;
    }
    float inv = (end > beg) ? 1.0f / (float)(end - beg) : 1.0f;
    acc.x *= inv; acc.y *= inv; acc.z *= inv; acc.w *= inv;
    *((float4*)(g_agg + (size_t)wid * FEAT) + lane) = acc;
}

// ---------------------------------------------------------------------------
// Aggregate layer 2: 16 lanes per node, mean of g_z[src] rows -> g_zagg.
// ---------------------------------------------------------------------------
__global__ void aggregate2_kernel() {
    int gt   = blockIdx.x * blockDim.x + threadIdx.x;
    int node = gt >> 4;
    int lane = gt & 15;
    if (node >= N_NODES) return;
    int beg = __ldg(g_row_ptr + node), end = __ldg(g_row_ptr + node + 1);

    float4 acc = make_float4(0.f, 0.f, 0.f, 0.f);
    int i = beg;
    for (; i + 4 <= end; i += 4) {
        int s0 = __ldg(g_col + i),     s1 = __ldg(g_col + i + 1);
        int s2 = __ldg(g_col + i + 2), s3 = __ldg(g_col + i + 3);
        float4 v0 = __ldg((const float4*)(g_z + (size_t)s0 * CLS) + lane);
        float4 v1 = __ldg((const float4*)(g_z + (size_t)s1 * CLS) + lane);
        float4 v2 = __ldg((const float4*)(g_z + (size_t)s2 * CLS) + lane);
        float4 v3 = __ldg((const float4*)(g_z + (size_t)s3 * CLS) + lane);
        acc.x += v0.x + v1.x + v2.x + v3.x;
        acc.y += v0.y + v1.y + v2.y + v3.y;
        acc.z += v0.z + v1.z + v2.z + v3.z;
        acc.w += v0.w + v1.w + v2.w + v3.w;
    }
    for (; i < end; i++) {
        int s = __ldg(g_col + i);
        float4 v = __ldg((const float4*)(g_z + (size_t)s * CLS) + lane);
        acc.x += v.x; acc.y += v.y; acc.z += v.z; acc.w += v.w;
    }
    float inv = (end > beg) ? 1.0f / (float)(end - beg) : 1.0f;
    acc.x *= inv; acc.y *= inv; acc.z *= inv; acc.w *= inv;
    *((float4*)(g_zagg + (size_t)node * CLS) + lane) = acc;
}

// ---------------------------------------------------------------------------
// TF32 tensor-core GEMMs (128x128 tile, 8 warps, m16n8k8, BK=16)
// ---------------------------------------------------------------------------
#define SMSTRIDE 20

__device__ __forceinline__ unsigned f2tf32(float f) {
    unsigned u;
    asm("cvt.rna.tf32.f32 %0, %1;" : "=r"(u) : "f"(f));
    return u;
}

#define MMA_TF32(c, a, b)                                                     \
    asm volatile("mma.sync.aligned.m16n8k8.row.col.f32.tf32.tf32.f32 "        \
                 "{%0,%1,%2,%3}, {%4,%5,%6,%7}, {%8,%9}, {%0,%1,%2,%3};"      \
                 : "+f"((c)[0]), "+f"((c)[1]), "+f"((c)[2]), "+f"((c)[3])     \
                 : "r"((a)[0]), "r"((a)[1]), "r"((a)[2]), "r"((a)[3]),        \
                   "r"((b)[0]), "r"((b)[1]))

// GEMM1: h = relu([mean | x] @ [W1l; W1r]^T + b1l), K = 256 (concat).
__global__ __launch_bounds__(256, 2)
void gemm1_tc(const float* __restrict__ x,
              const float* __restrict__ W1l,
              const float* __restrict__ b1l,
              const float* __restrict__ W1r) {
    __shared__ unsigned As[128 * SMSTRIDE];
    __shared__ unsigned Bs[128 * SMSTRIDE];

    int t    = threadIdx.x;
    int lane = t & 31, w = t >> 5;
    int g    = lane >> 2, tig = lane & 3;
    int wm   = w & 3, wn = w >> 2;
    int m0   = blockIdx.x * 128;

    float acc[2][8][4];
#pragma unroll
    for (int mt = 0; mt < 2; mt++)
#pragma unroll
        for (int nt = 0; nt < 8; nt++)
#pragma unroll
            for (int i = 0; i < 4; i++) acc[mt][nt][i] = 0.f;

    int lrow = t >> 1;
    int lk   = (t & 1) * 8;
    int arow = m0 + lrow;
    bool valid = arow < N_NODES;

    unsigned stA[8], stB[8];

    auto load_tile = [&](int kt) {
        const float* Asrc = (kt < 128) ? g_agg : x;
        int ak = (kt < 128) ? kt : (kt - 128);
        float4 a0, a1;
        if (valid) {
            const float4* ap = (const float4*)(Asrc + (size_t)arow * FEAT + ak + lk);
            a0 = __ldg(ap); a1 = __ldg(ap + 1);
        } else {
            a0 = make_float4(0.f, 0.f, 0.f, 0.f); a1 = a0;
        }
        stA[0] = f2tf32(a0.x); stA[1] = f2tf32(a0.y);
        stA[2] = f2tf32(a0.z); stA[3] = f2tf32(a0.w);
        stA[4] = f2tf32(a1.x); stA[5] = f2tf32(a1.y);
        stA[6] = f2tf32(a1.z); stA[7] = f2tf32(a1.w);

        const float* Wsrc = (kt < 128) ? W1l : W1r;
        const float4* bp = (const float4*)(Wsrc + (size_t)lrow * FEAT + ak + lk);
        float4 b0 = __ldg(bp), b1 = __ldg(bp + 1);
        stB[0] = f2tf32(b0.x); stB[1] = f2tf32(b0.y);
        stB[2] = f2tf32(b0.z); stB[3] = f2tf32(b0.w);
        stB[4] = f2tf32(b1.x); stB[5] = f2tf32(b1.y);
        stB[6] = f2tf32(b1.z); stB[7] = f2tf32(b1.w);
    };

    load_tile(0);

    for (int kt = 0; kt < 256; kt += 16) {
        __syncthreads();
        {
            unsigned* pa = &As[lrow * SMSTRIDE + lk];
            *(uint4*)pa       = make_uint4(stA[0], stA[1], stA[2], stA[3]);
            *(uint4*)(pa + 4) = make_uint4(stA[4], stA[5], stA[6], stA[7]);
            unsigned* pb = &Bs[lrow * SMSTRIDE + lk];
            *(uint4*)pb       = make_uint4(stB[0], stB[1], stB[2], stB[3]);
            *(uint4*)(pb + 4) = make_uint4(stB[4], stB[5], stB[6], stB[7]);
        }
        __syncthreads();
        if (kt + 16 < 256) load_tile(kt + 16);

#pragma unroll
        for (int ks = 0; ks < 2; ks++) {
            int k0 = ks * 8;
            unsigned afr[2][4], bfr[8][2];
#pragma unroll
            for (int mt = 0; mt < 2; mt++) {
                int r = wm * 32 + mt * 16 + g;
                afr[mt][0] = As[r * SMSTRIDE + k0 + tig];
                afr[mt][1] = As[(r + 8) * SMSTRIDE + k0 + tig];
                afr[mt][2] = As[r * SMSTRIDE + k0 + tig + 4];
                afr[mt][3] = As[(r + 8) * SMSTRIDE + k0 + tig + 4];
            }
#pragma unroll
            for (int nt = 0; nt < 8; nt++) {
                int c = wn * 64 + nt * 8 + g;
                bfr[nt][0] = Bs[c * SMSTRIDE + k0 + tig];
                bfr[nt][1] = Bs[c * SMSTRIDE + k0 + tig + 4];
            }
#pragma unroll
            for (int mt = 0; mt < 2; mt++)
#pragma unroll
                for (int nt = 0; nt < 8; nt++)
                    MMA_TF32(acc[mt][nt], afr[mt], bfr[nt]);
        }
    }

#pragma unroll
    for (int nt = 0; nt < 8; nt++) {
        int col = wn * 64 + nt * 8 + 2 * tig;
        float2 bias = __ldg((const float2*)(b1l + col));
#pragma unroll
        for (int mt = 0; mt < 2; mt++) {
            int r = m0 + wm * 32 + mt * 16 + g;
            if (r < N_NODES) {
                float2 o;
                o.x = fmaxf(acc[mt][nt][0] + bias.x, 0.f);
                o.y = fmaxf(acc[mt][nt][1] + bias.y, 0.f);
                *(float2*)(g_h + (size_t)r * FEAT + col) = o;
            }
            if (r + 8 < N_NODES) {
                float2 o;
                o.x = fmaxf(acc[mt][nt][2] + bias.x, 0.f);
                o.y = fmaxf(acc[mt][nt][3] + bias.y, 0.f);
                *(float2*)(g_h + (size_t)(r + 8) * FEAT + col) = o;
            }
        }
    }
}

// GEMM2: y = h @ [W2l; W2r]^T (K = 128). Cols <64 -> g_z, >=64 -> g_r.
__global__ __launch_bounds__(256, 2)
void gemm2_tc(const float* __restrict__ W2l,
              const float* __restrict__ W2r) {
    __shared__ unsigned As[128 * SMSTRIDE];
    __shared__ unsigned Bs[128 * SMSTRIDE];

    int t    = threadIdx.x;
    int lane = t & 31, w = t >> 5;
    int g    = lane >> 2, tig = lane & 3;
    int wm   = w & 3, wn = w >> 2;
    int m0   = blockIdx.x * 128;

    float acc[2][8][4];
#pragma unroll
    for (int mt = 0; mt < 2; mt++)
#pragma unroll
        for (int nt = 0; nt < 8; nt++)
#pragma unroll
            for (int i = 0; i < 4; i++) acc[mt][nt][i] = 0.f;

    int lrow = t >> 1;
    int lk   = (t & 1) * 8;
    int arow = m0 + lrow;
    bool valid = arow < N_NODES;
    const float* Wrow = (lrow < 64) ? (W2l + (size_t)lrow * FEAT)
                                    : (W2r + (size_t)(lrow - 64) * FEAT);

    unsigned stA[8], stB[8];

    auto load_tile = [&](int kt) {
        float4 a0, a1;
        if (valid) {
            const float4* ap = (const float4*)(g_h + (size_t)arow * FEAT + kt + lk);
            a0 = __ldg(ap); a1 = __ldg(ap + 1);
        } else {
            a0 = make_float4(0.f, 0.f, 0.f, 0.f); a1 = a0;
        }
        stA[0] = f2tf32(a0.x); stA[1] = f2tf32(a0.y);
        stA[2] = f2tf32(a0.z); stA[3] = f2tf32(a0.w);
        stA[4] = f2tf32(a1.x); stA[5] = f2tf32(a1.y);
        stA[6] = f2tf32(a1.z); stA[7] = f2tf32(a1.w);

        const float4* bp = (const float4*)(Wrow + kt + lk);
        float4 b0 = __ldg(bp), b1 = __ldg(bp + 1);
        stB[0] = f2tf32(b0.x); stB[1] = f2tf32(b0.y);
        stB[2] = f2tf32(b0.z); stB[3] = f2tf32(b0.w);
        stB[4] = f2tf32(b1.x); stB[5] = f2tf32(b1.y);
        stB[6] = f2tf32(b1.z); stB[7] = f2tf32(b1.w);
    };

    load_tile(0);

    for (int kt = 0; kt < 128; kt += 16) {
        __syncthreads();
        {
            unsigned* pa = &As[lrow * SMSTRIDE + lk];
            *(uint4*)pa       = make_uint4(stA[0], stA[1], stA[2], stA[3]);
            *(uint4*)(pa + 4) = make_uint4(stA[4], stA[5], stA[6], stA[7]);
            unsigned* pb = &Bs[lrow * SMSTRIDE + lk];
            *(uint4*)pb       = make_uint4(stB[0], stB[1], stB[2], stB[3]);
            *(uint4*)(pb + 4) = make_uint4(stB[4], stB[5], stB[6], stB[7]);
        }
        __syncthreads();
        if (kt + 16 < 128) load_tile(kt + 16);

#pragma unroll
        for (int ks = 0; ks < 2; ks++) {
            int k0 = ks * 8;
            unsigned afr[2][4], bfr[8][2];
#pragma unroll
            for (int mt = 0; mt < 2; mt++) {
                int r = wm * 32 + mt * 16 + g;
                afr[mt][0] = As[r * SMSTRIDE + k0 + tig];
                afr[mt][1] = As[(r + 8) * SMSTRIDE + k0 + tig];
                afr[mt][2] = As[r * SMSTRIDE + k0 + tig + 4];
                afr[mt][3] = As[(r + 8) * SMSTRIDE + k0 + tig + 4];
            }
#pragma unroll
            for (int nt = 0; nt < 8; nt++) {
                int c = wn * 64 + nt * 8 + g;
                bfr[nt][0] = Bs[c * SMSTRIDE + k0 + tig];
                bfr[nt][1] = Bs[c * SMSTRIDE + k0 + tig + 4];
            }
#pragma unroll
            for (int mt = 0; mt < 2; mt++)
#pragma unroll
                for (int nt = 0; nt < 8; nt++)
                    MMA_TF32(acc[mt][nt], afr[mt], bfr[nt]);
        }
    }

#pragma unroll
    for (int nt = 0; nt < 8; nt++) {
        int col = wn * 64 + nt * 8 + 2 * tig;
        float* dst = (col < 64) ? g_z : g_r;
        int c2 = (col < 64) ? col : col - 64;
#pragma unroll
        for (int mt = 0; mt < 2; mt++) {
            int r = m0 + wm * 32 + mt * 16 + g;
            if (r < N_NODES) {
                float2 o = make_float2(acc[mt][nt][0], acc[mt][nt][1]);
                *(float2*)(dst + (size_t)r * CLS + c2) = o;
            }
            if (r + 8 < N_NODES) {
                float2 o = make_float2(acc[mt][nt][2], acc[mt][nt][3]);
                *(float2*)(dst + (size_t)(r + 8) * CLS + c2) = o;
            }
        }
    }
}

// ---------------------------------------------------------------------------
// Final: out = log_softmax(zmean + b2l + r). 16 lanes per node.
// ---------------------------------------------------------------------------
__global__ void final_kernel(const float* __restrict__ b2l,
                             float* __restrict__ out) {
    int gt   = blockIdx.x * blockDim.x + threadIdx.x;
    int m    = gt >> 4;
    int lane = gt & 15;
    if (m >= N_NODES) return;

    float4 za = *(const float4*)(g_zagg + (size_t)m * CLS + lane * 4);
    float4 r  = *(const float4*)(g_r   + (size_t)m * CLS + lane * 4);
    float4 bb = __ldg((const float4*)(b2l + lane * 4));

    float v[4];
    v[0] = za.x + bb.x + r.x;
    v[1] = za.y + bb.y + r.y;
    v[2] = za.z + bb.z + r.z;
    v[3] = za.w + bb.w + r.w;

    float rmax = fmaxf(fmaxf(v[0], v[1]), fmaxf(v[2], v[3]));
#pragma unroll
    for (int off = 8; off > 0; off >>= 1)
        rmax = fmaxf(rmax, __shfl_xor_sync(0xffffffffu, rmax, off));
    float s = expf(v[0] - rmax) + expf(v[1] - rmax)
            + expf(v[2] - rmax) + expf(v[3] - rmax);
#pragma unroll
    for (int off = 8; off > 0; off >>= 1)
        s += __shfl_xor_sync(0xffffffffu, s, off);
    float lse = logf(s) + rmax;

    float4 o;
    o.x = v[0] - lse; o.y = v[1] - lse; o.z = v[2] - lse; o.w = v[3] - lse;
    *(float4*)(out + (size_t)m * CLS + lane * 4) = o;
}

// ---------------------------------------------------------------------------
// Launch
// ---------------------------------------------------------------------------
extern "C" void kernel_launch(void* const* d_in, const int* in_sizes, int n_in,
                              void* d_out, int out_size) {
    const float* x    = (const float*)d_in[0];
    const int*   ei   = (const int*)d_in[1];
    const float* W1l  = (const float*)d_in[2];
    const float* b1l  = (const float*)d_in[3];
    const float* W1r  = (const float*)d_in[4];
    const float* W2l  = (const float*)d_in[5];
    const float* b2l  = (const float*)d_in[6];
    const float* W2r  = (const float*)d_in[7];
    float*       out  = (float*)d_out;

    const int n_edges = in_sizes[1] / 2;
    const int* srcs = ei;
    const int* dsts = ei + n_edges;

    const int edge_blocks = (n_edges + 255) / 256;
    const int node_blocks = (N_NODES + 255) / 256;
    const int agg1_blocks = (N_NODES * 32 + 255) / 256;
    const int agg2_blocks = (N_NODES * 16 + 255) / 256;
    const int gemm_blocks = (N_NODES + 127) / 128;
    const int fin_blocks  = (N_NODES * 16 + 255) / 256;

    // CSR build
    zero_hist_kernel<<<node_blocks, 256>>>();
    hist_kernel<<<edge_blocks, 256>>>(srcs, dsts, n_edges);
    scan_a_kernel<<<SCAN_BLOCKS, 256>>>();
    scan_b_kernel<<<1, 256>>>();
    scan_c_kernel<<<SCAN_BLOCKS, 256>>>();
    fill_kernel<<<edge_blocks, 256>>>(srcs, dsts, n_edges);

    // Layer 1
    aggregate1_kernel<<<agg1_blocks, 256>>>(x);
    gemm1_tc<<<gemm_blocks, 256>>>(x, W1l, b1l, W1r);

    // Layer 2
    gemm2_tc<<<gemm_blocks, 256>>>(W2l, W2r);
    aggregate2_kernel<<<agg2_blocks, 256>>>();
    final_kernel<<<fin_blocks, 256>>>(b2l, out);
}

// round 6
// speedup vs baseline: 4.4483x; 1.5747x over previous
#include <cuda_runtime.h>

#define N_NODES 100000
#define FEAT    128
#define CLS     64
#define MAX_EDGES 1700000

// Scratch (allocation-free rule: __device__ globals)
__device__ float g_agg[(size_t)N_NODES * FEAT];   // layer-1 mean aggregation
__device__ float g_h[(size_t)N_NODES * FEAT];     // layer-1 activations
__device__ float g_z[(size_t)N_NODES * CLS];      // h @ W2l^T (pre-aggregation)
__device__ float g_r[(size_t)N_NODES * CLS];      // h @ W2r^T (self term)
// CSR machinery
__device__ int g_hist[N_NODES];
__device__ int g_row_ptr[N_NODES + 1];
__device__ int g_cursor[N_NODES];
__device__ int g_col[MAX_EDGES];
__device__ int g_part[256];
__device__ int g_part_scan[256];
__device__ int g_total;

#define SCAN_BLOCKS 200
#define SCAN_CHUNK  512

// ---------------------------------------------------------------------------
// CSR build
// ---------------------------------------------------------------------------
__global__ void zero_hist_kernel() {
    int i = blockIdx.x * blockDim.x + threadIdx.x;
    if (i < N_NODES) g_hist[i] = 0;
}

__global__ void hist_kernel(const int* __restrict__ srcs,
                            const int* __restrict__ dsts, int n_edges) {
    int e = blockIdx.x * blockDim.x + threadIdx.x;
    if (e >= n_edges) return;
    int s = __ldg(srcs + e);
    int d = __ldg(dsts + e);
    if ((unsigned)s >= N_NODES || (unsigned)d >= N_NODES) return;
    atomicAdd(g_hist + d, 1);
}

__global__ void scan_a_kernel() {
    __shared__ int sm[256];
    int b = blockIdx.x, t = threadIdx.x;
    int i0 = b * SCAN_CHUNK + t;
    int i1 = i0 + 256;
    int v = 0;
    if (i0 < N_NODES) v += g_hist[i0];
    if (i1 < N_NODES) v += g_hist[i1];
    sm[t] = v;
    __syncthreads();
#pragma unroll
    for (int off = 128; off > 0; off >>= 1) {
        if (t < off) sm[t] += sm[t + off];
        __syncthreads();
    }
    if (t == 0) g_part[b] = sm[0];
}

__global__ void scan_b_kernel() {
    __shared__ int sm[256];
    int t = threadIdx.x;
    int v = (t < SCAN_BLOCKS) ? g_part[t] : 0;
    sm[t] = v;
    __syncthreads();
#pragma unroll
    for (int off = 1; off < 256; off <<= 1) {
        int add = (t >= off) ? sm[t - off] : 0;
        __syncthreads();
        sm[t] += add;
        __syncthreads();
    }
    if (t < SCAN_BLOCKS) g_part_scan[t] = sm[t] - v;
    if (t == 0) g_total = sm[255];
}

__global__ void scan_c_kernel() {
    __shared__ int sm[256];
    int b = blockIdx.x, t = threadIdx.x;
    int base = b * SCAN_CHUNK + 2 * t;
    int a0 = (base     < N_NODES) ? g_hist[base]     : 0;
    int a1 = (base + 1 < N_NODES) ? g_hist[base + 1] : 0;
    int s = a0 + a1;
    sm[t] = s;
    __syncthreads();
#pragma unroll
    for (int off = 1; off < 256; off <<= 1) {
        int add = (t >= off) ? sm[t - off] : 0;
        __syncthreads();
        sm[t] += add;
        __syncthreads();
    }
    int offset = g_part_scan[b] + sm[t] - s;
    if (base < N_NODES) {
        g_row_ptr[base] = offset;
        g_cursor[base]  = offset;
    }
    if (base + 1 < N_NODES) {
        g_row_ptr[base + 1] = offset + a0;
        g_cursor[base + 1]  = offset + a0;
    }
    if (b == 0 && t == 0) g_row_ptr[N_NODES] = g_total;
}

__global__ void fill_kernel(const int* __restrict__ srcs,
                            const int* __restrict__ dsts, int n_edges) {
    int e = blockIdx.x * blockDim.x + threadIdx.x;
    if (e >= n_edges) return;
    int s = __ldg(srcs + e);
    int d = __ldg(dsts + e);
    if ((unsigned)s >= N_NODES || (unsigned)d >= N_NODES) return;
    int pos = atomicAdd(g_cursor + d, 1);
    g_col[pos] = s;
}

// ---------------------------------------------------------------------------
// Aggregate layer 1: warp per node, mean of x[src] rows -> g_agg.
// ---------------------------------------------------------------------------
__global__ void aggregate1_kernel(const float* __restrict__ x) {
    int wid  = (blockIdx.x * blockDim.x + threadIdx.x) >> 5;
    int lane = threadIdx.x & 31;
    if (wid >= N_NODES) return;
    int beg = __ldg(g_row_ptr + wid), end = __ldg(g_row_ptr + wid + 1);

    float4 acc = make_float4(0.f, 0.f, 0.f, 0.f);
    int i = beg;
    for (; i + 4 <= end; i += 4) {
        int s0 = __ldg(g_col + i),     s1 = __ldg(g_col + i + 1);
        int s2 = __ldg(g_col + i + 2), s3 = __ldg(g_col + i + 3);
        float4 v0 = __ldg((const float4*)(x + (size_t)s0 * FEAT) + lane);
        float4 v1 = __ldg((const float4*)(x + (size_t)s1 * FEAT) + lane);
        float4 v2 = __ldg((const float4*)(x + (size_t)s2 * FEAT) + lane);
        float4 v3 = __ldg((const float4*)(x + (size_t)s3 * FEAT) + lane);
        acc.x += v0.x + v1.x + v2.x + v3.x;
        acc.y += v0.y + v1.y + v2.y + v3.y;
        acc.z += v0.z + v1.z + v2.z + v3.z;
        acc.w += v0.w + v1.w + v2.w + v3.w;
    }
    for (; i < end; i++) {
        int s = __ldg(g_col + i);
        float4 v = __ldg((const float4*)(x + (size_t)s * FEAT) + lane);
        acc.x += v.x; acc.y += v.y; acc.z += v.z; acc.w += v.w;
    }
    float inv = (end > beg) ? 1.0f / (float)(end - beg) : 1.0f;
    acc.x *= inv; acc.y *= inv; acc.z *= inv; acc.w *= inv;
    *((float4*)(g_agg + (size_t)wid * FEAT) + lane) = acc;
}

// ---------------------------------------------------------------------------
// TF32 tensor-core GEMMs with cp.async double buffering
//   Block tile 128x128, 8 warps (4Mx2N), warp tile 32x64, BK=32, 2 stages.
//   smem rows padded to 36 floats. Raw fp32 bits fed to tf32 MMA (HW truncates).
// ---------------------------------------------------------------------------
#define SMST   36
#define TILE_F (128 * SMST)          // floats per matrix tile (4608)
#define STAGE_F (2 * TILE_F)         // floats per stage (A+B)
#define GSMEM_BYTES (2 * STAGE_F * 4)  // 73728

#define MMA_TF32(c, a, b)                                                     \
    asm volatile("mma.sync.aligned.m16n8k8.row.col.f32.tf32.tf32.f32 "        \
                 "{%0,%1,%2,%3}, {%4,%5,%6,%7}, {%8,%9}, {%0,%1,%2,%3};"      \
                 : "+f"((c)[0]), "+f"((c)[1]), "+f"((c)[2]), "+f"((c)[3])     \
                 : "r"((a)[0]), "r"((a)[1]), "r"((a)[2]), "r"((a)[3]),        \
                   "r"((b)[0]), "r"((b)[1]))

__device__ __forceinline__ void cp_async16(unsigned saddr, const void* gptr, int ssize) {
    asm volatile("cp.async.cg.shared.global [%0], [%1], 16, %2;"
                 :: "r"(saddr), "l"(gptr), "r"(ssize));
}
__device__ __forceinline__ void cp_commit() {
    asm volatile("cp.async.commit_group;");
}
template <int N>
__device__ __forceinline__ void cp_wait() {
    asm volatile("cp.async.wait_group %0;" :: "n"(N));
}

// ---- shared compute step: 1 BK=32 tile of MMAs ----
__device__ __forceinline__ void mma_tile(const unsigned* As, const unsigned* Bs,
                                         int wm, int wn, int g, int tig,
                                         float acc[2][8][4]) {
#pragma unroll
    for (int ks = 0; ks < 4; ks++) {
        int k0 = ks * 8;
        unsigned afr[2][4], bfr[8][2];
#pragma unroll
        for (int mt = 0; mt < 2; mt++) {
            int r = wm * 32 + mt * 16 + g;
            afr[mt][0] = As[r * SMST + k0 + tig];
            afr[mt][1] = As[(r + 8) * SMST + k0 + tig];
            afr[mt][2] = As[r * SMST + k0 + tig + 4];
            afr[mt][3] = As[(r + 8) * SMST + k0 + tig + 4];
        }
#pragma unroll
        for (int nt = 0; nt < 8; nt++) {
            int c = wn * 64 + nt * 8 + g;
            bfr[nt][0] = Bs[c * SMST + k0 + tig];
            bfr[nt][1] = Bs[c * SMST + k0 + tig + 4];
        }
#pragma unroll
        for (int mt = 0; mt < 2; mt++)
#pragma unroll
            for (int nt = 0; nt < 8; nt++)
                MMA_TF32(acc[mt][nt], afr[mt], bfr[nt]);
    }
}

// GEMM1: h = relu([mean | x] @ [W1l; W1r]^T + b1l), K = 256 (concat).
__global__ __launch_bounds__(256, 2)
void gemm1_tc(const float* __restrict__ x,
              const float* __restrict__ W1l,
              const float* __restrict__ b1l,
              const float* __restrict__ W1r) {
    extern __shared__ float smem[];

    int t    = threadIdx.x;
    int lane = t & 31, w = t >> 5;
    int g    = lane >> 2, tig = lane & 3;
    int wm   = w & 3, wn = w >> 2;
    int m0   = blockIdx.x * 128;

    float acc[2][8][4];
#pragma unroll
    for (int mt = 0; mt < 2; mt++)
#pragma unroll
        for (int nt = 0; nt < 8; nt++)
#pragma unroll
            for (int i = 0; i < 4; i++) acc[mt][nt][i] = 0.f;

    unsigned sbase = (unsigned)__cvta_generic_to_shared(smem);

    // copy one BK=32 tile (tile idx 0..7) into stage buf
    auto copy_tile = [&](int tile, int buf) {
        int kt = tile * 32;
        const float* Asrc = (kt < 128) ? g_agg : x;
        int ak = (kt < 128) ? kt : kt - 128;
        const float* Wsrc = (kt < 128) ? W1l : W1r;
        unsigned abase = sbase + buf * STAGE_F * 4;
        unsigned bbase = abase + TILE_F * 4;
#pragma unroll
        for (int c = 0; c < 4; c++) {
            int cid = t * 4 + c;          // 0..1023
            int row = cid >> 3, ch = cid & 7;
            int arow = m0 + row;
            int ssz = (arow < N_NODES) ? 16 : 0;
            int crow = (arow < N_NODES) ? arow : (N_NODES - 1);
            cp_async16(abase + (row * SMST + ch * 4) * 4,
                       Asrc + (size_t)crow * FEAT + ak + ch * 4, ssz);
            cp_async16(bbase + (row * SMST + ch * 4) * 4,
                       Wsrc + (size_t)row * FEAT + ak + ch * 4, 16);
        }
    };

    copy_tile(0, 0);
    cp_commit();

#pragma unroll 1
    for (int tile = 0; tile < 8; tile++) {
        if (tile + 1 < 8) {
            copy_tile(tile + 1, (tile + 1) & 1);
            cp_commit();
            cp_wait<1>();
        } else {
            cp_wait<0>();
        }
        __syncthreads();
        const unsigned* As = (const unsigned*)(smem + (tile & 1) * STAGE_F);
        const unsigned* Bs = As + TILE_F;
        mma_tile(As, Bs, wm, wn, g, tig, acc);
        __syncthreads();
    }

#pragma unroll
    for (int nt = 0; nt < 8; nt++) {
        int col = wn * 64 + nt * 8 + 2 * tig;
        float2 bias = __ldg((const float2*)(b1l + col));
#pragma unroll
        for (int mt = 0; mt < 2; mt++) {
            int r = m0 + wm * 32 + mt * 16 + g;
            if (r < N_NODES) {
                float2 o;
                o.x = fmaxf(acc[mt][nt][0] + bias.x, 0.f);
                o.y = fmaxf(acc[mt][nt][1] + bias.y, 0.f);
                *(float2*)(g_h + (size_t)r * FEAT + col) = o;
            }
            if (r + 8 < N_NODES) {
                float2 o;
                o.x = fmaxf(acc[mt][nt][2] + bias.x, 0.f);
                o.y = fmaxf(acc[mt][nt][3] + bias.y, 0.f);
                *(float2*)(g_h + (size_t)(r + 8) * FEAT + col) = o;
            }
        }
    }
}

// GEMM2: y = h @ [W2l; W2r]^T (K = 128). Cols <64 -> g_z, >=64 -> g_r.
__global__ __launch_bounds__(256, 2)
void gemm2_tc(const float* __restrict__ W2l,
              const float* __restrict__ W2r) {
    extern __shared__ float smem[];

    int t    = threadIdx.x;
    int lane = t & 31, w = t >> 5;
    int g    = lane >> 2, tig = lane & 3;
    int wm   = w & 3, wn = w >> 2;
    int m0   = blockIdx.x * 128;

    float acc[2][8][4];
#pragma unroll
    for (int mt = 0; mt < 2; mt++)
#pragma unroll
        for (int nt = 0; nt < 8; nt++)
#pragma unroll
            for (int i = 0; i < 4; i++) acc[mt][nt][i] = 0.f;

    unsigned sbase = (unsigned)__cvta_generic_to_shared(smem);

    auto copy_tile = [&](int tile, int buf) {
        int kt = tile * 32;
        unsigned abase = sbase + buf * STAGE_F * 4;
        unsigned bbase = abase + TILE_F * 4;
#pragma unroll
        for (int c = 0; c < 4; c++) {
            int cid = t * 4 + c;
            int row = cid >> 3, ch = cid & 7;
            int arow = m0 + row;
            int ssz = (arow < N_NODES) ? 16 : 0;
            int crow = (arow < N_NODES) ? arow : (N_NODES - 1);
            cp_async16(abase + (row * SMST + ch * 4) * 4,
                       g_h + (size_t)crow * FEAT + kt + ch * 4, ssz);
            const float* Wrow = (row < 64) ? (W2l + (size_t)row * FEAT)
                                           : (W2r + (size_t)(row - 64) * FEAT);
            cp_async16(bbase + (row * SMST + ch * 4) * 4,
                       Wrow + kt + ch * 4, 16);
        }
    };

    copy_tile(0, 0);
    cp_commit();

#pragma unroll 1
    for (int tile = 0; tile < 4; tile++) {
        if (tile + 1 < 4) {
            copy_tile(tile + 1, (tile + 1) & 1);
            cp_commit();
            cp_wait<1>();
        } else {
            cp_wait<0>();
        }
        __syncthreads();
        const unsigned* As = (const unsigned*)(smem + (tile & 1) * STAGE_F);
        const unsigned* Bs = As + TILE_F;
        mma_tile(As, Bs, wm, wn, g, tig, acc);
        __syncthreads();
    }

#pragma unroll
    for (int nt = 0; nt < 8; nt++) {
        int col = wn * 64 + nt * 8 + 2 * tig;
        float* dst = (col < 64) ? g_z : g_r;
        int c2 = (col < 64) ? col : col - 64;
#pragma unroll
        for (int mt = 0; mt < 2; mt++) {
            int r = m0 + wm * 32 + mt * 16 + g;
            if (r < N_NODES) {
                float2 o = make_float2(acc[mt][nt][0], acc[mt][nt][1]);
                *(float2*)(dst + (size_t)r * CLS + c2) = o;
            }
            if (r + 8 < N_NODES) {
                float2 o = make_float2(acc[mt][nt][2], acc[mt][nt][3]);
                *(float2*)(dst + (size_t)(r + 8) * CLS + c2) = o;
            }
        }
    }
}

// ---------------------------------------------------------------------------
// Fused aggregate2 + bias + self-term + log_softmax + store. 16 lanes/node.
// ---------------------------------------------------------------------------
__global__ void agg2_final_kernel(const float* __restrict__ b2l,
                                  float* __restrict__ out) {
    int gt   = blockIdx.x * blockDim.x + threadIdx.x;
    int node = gt >> 4;
    int lane = gt & 15;
    if (node >= N_NODES) return;
    int beg = __ldg(g_row_ptr + node), end = __ldg(g_row_ptr + node + 1);

    float4 acc = make_float4(0.f, 0.f, 0.f, 0.f);
    int i = beg;
    for (; i + 4 <= end; i += 4) {
        int s0 = __ldg(g_col + i),     s1 = __ldg(g_col + i + 1);
        int s2 = __ldg(g_col + i + 2), s3 = __ldg(g_col + i + 3);
        float4 v0 = __ldg((const float4*)(g_z + (size_t)s0 * CLS) + lane);
        float4 v1 = __ldg((const float4*)(g_z + (size_t)s1 * CLS) + lane);
        float4 v2 = __ldg((const float4*)(g_z + (size_t)s2 * CLS) + lane);
        float4 v3 = __ldg((const float4*)(g_z + (size_t)s3 * CLS) + lane);
        acc.x += v0.x + v1.x + v2.x + v3.x;
        acc.y += v0.y + v1.y + v2.y + v3.y;
        acc.z += v0.z + v1.z + v2.z + v3.z;
        acc.w += v0.w + v1.w + v2.w + v3.w;
    }
    for (; i < end; i++) {
        int s = __ldg(g_col + i);
        float4 v = __ldg((const float4*)(g_z + (size_t)s * CLS) + lane);
        acc.x += v.x; acc.y += v.y; acc.z += v.z; acc.w += v.w;
    }
    float inv = (end > beg) ? 1.0f / (float)(end - beg) : 1.0f;

    float4 r  = *(const float4*)(g_r + (size_t)node * CLS + lane * 4);
    float4 bb = __ldg((const float4*)(b2l + lane * 4));

    float v[4];
    v[0] = acc.x * inv + bb.x + r.x;
    v[1] = acc.y * inv + bb.y + r.y;
    v[2] = acc.z * inv + bb.z + r.z;
    v[3] = acc.w * inv + bb.w + r.w;

    float rmax = fmaxf(fmaxf(v[0], v[1]), fmaxf(v[2], v[3]));
#pragma unroll
    for (int off = 8; off > 0; off >>= 1)
        rmax = fmaxf(rmax, __shfl_xor_sync(0xffffffffu, rmax, off));
    float s = expf(v[0] - rmax) + expf(v[1] - rmax)
            + expf(v[2] - rmax) + expf(v[3] - rmax);
#pragma unroll
    for (int off = 8; off > 0; off >>= 1)
        s += __shfl_xor_sync(0xffffffffu, s, off);
    float lse = logf(s) + rmax;

    float4 o;
    o.x = v[0] - lse; o.y = v[1] - lse; o.z = v[2] - lse; o.w = v[3] - lse;
    *(float4*)(out + (size_t)node * CLS + lane * 4) = o;
}

// ---------------------------------------------------------------------------
// Launch
// ---------------------------------------------------------------------------
extern "C" void kernel_launch(void* const* d_in, const int* in_sizes, int n_in,
                              void* d_out, int out_size) {
    const float* x    = (const float*)d_in[0];
    const int*   ei   = (const int*)d_in[1];
    const float* W1l  = (const float*)d_in[2];
    const float* b1l  = (const float*)d_in[3];
    const float* W1r  = (const float*)d_in[4];
    const float* W2l  = (const float*)d_in[5];
    const float* b2l  = (const float*)d_in[6];
    const float* W2r  = (const float*)d_in[7];
    float*       out  = (float*)d_out;

    const int n_edges = in_sizes[1] / 2;
    const int* srcs = ei;
    const int* dsts = ei + n_edges;

    const int edge_blocks = (n_edges + 255) / 256;
    const int node_blocks = (N_NODES + 255) / 256;
    const int agg1_blocks = (N_NODES * 32 + 255) / 256;
    const int gemm_blocks = (N_NODES + 127) / 128;
    const int fin_blocks  = (N_NODES * 16 + 255) / 256;

    static int smem_set = 0;
    if (!smem_set) {
        cudaFuncSetAttribute(gemm1_tc, cudaFuncAttributeMaxDynamicSharedMemorySize, GSMEM_BYTES);
        cudaFuncSetAttribute(gemm2_tc, cudaFuncAttributeMaxDynamicSharedMemorySize, GSMEM_BYTES);
        smem_set = 1;
    }

    // CSR build
    zero_hist_kernel<<<node_blocks, 256>>>();
    hist_kernel<<<edge_blocks, 256>>>(srcs, dsts, n_edges);
    scan_a_kernel<<<SCAN_BLOCKS, 256>>>();
    scan_b_kernel<<<1, 256>>>();
    scan_c_kernel<<<SCAN_BLOCKS, 256>>>();
    fill_kernel<<<edge_blocks, 256>>>(srcs, dsts, n_edges);

    // Layer 1
    aggregate1_kernel<<<agg1_blocks, 256>>>(x);
    gemm1_tc<<<gemm_blocks, 256, GSMEM_BYTES>>>(x, W1l, b1l, W1r);

    // Layer 2
    gemm2_tc<<<gemm_blocks, 256, GSMEM_BYTES>>>(W2l, W2r);
    agg2_final_kernel<<<fin_blocks, 256>>>(b2l, out);
}

// round 7
// speedup vs baseline: 4.5560x; 1.0242x over previous
#include <cuda_runtime.h>
#include <cuda_fp16.h>

#define N_NODES 100000
#define FEAT    128
#define CLS     64
#define MAX_EDGES 1700000

// Scratch (allocation-free rule: __device__ globals)
__device__ float   g_agg[(size_t)N_NODES * FEAT]; // layer-1 mean aggregation (fp32)
__device__ float   g_h[(size_t)N_NODES * FEAT];   // layer-1 activations
__device__ __half2 g_xh[(size_t)N_NODES * 64];    // x in half (128 halves/row)
__device__ __half2 g_zh[(size_t)N_NODES * 32];    // h @ W2l^T in half (64 halves/row)
__device__ float   g_r[(size_t)N_NODES * CLS];    // h @ W2r^T (self term, fp32)
// CSR machinery
__device__ int g_hist[N_NODES];
__device__ int g_row_ptr[N_NODES + 1];
__device__ int g_cursor[N_NODES];
__device__ int g_col[MAX_EDGES];
__device__ int g_part[256];
__device__ int g_part_scan[256];
__device__ int g_total;

#define SCAN_BLOCKS 200
#define SCAN_CHUNK  512

// ---------------------------------------------------------------------------
// Convert x -> half copy; also zero the degree histogram (fused).
// One thread handles 8 floats. Threads = N_NODES * 16.
// ---------------------------------------------------------------------------
__global__ void convert_x_kernel(const float* __restrict__ x) {
    int idx = blockIdx.x * blockDim.x + threadIdx.x;
    const int total = N_NODES * 16;
    if (idx < total) {
        const float4* src = (const float4*)x + idx * 2;
        float4 a = __ldg(src), b = __ldg(src + 1);
        __half2 h0 = __floats2half2_rn(a.x, a.y);
        __half2 h1 = __floats2half2_rn(a.z, a.w);
        __half2 h2 = __floats2half2_rn(b.x, b.y);
        __half2 h3 = __floats2half2_rn(b.z, b.w);
        uint4 packed = make_uint4(*(unsigned*)&h0, *(unsigned*)&h1,
                                  *(unsigned*)&h2, *(unsigned*)&h3);
        *((uint4*)g_xh + idx) = packed;
    }
    if (idx < N_NODES) g_hist[idx] = 0;
}

// ---------------------------------------------------------------------------
// CSR build
// ---------------------------------------------------------------------------
__global__ void hist_kernel(const int* __restrict__ srcs,
                            const int* __restrict__ dsts, int n_edges) {
    int e = blockIdx.x * blockDim.x + threadIdx.x;
    if (e >= n_edges) return;
    int s = __ldg(srcs + e);
    int d = __ldg(dsts + e);
    if ((unsigned)s >= N_NODES || (unsigned)d >= N_NODES) return;
    atomicAdd(g_hist + d, 1);
}

__global__ void scan_a_kernel() {
    __shared__ int sm[256];
    int b = blockIdx.x, t = threadIdx.x;
    int i0 = b * SCAN_CHUNK + t;
    int i1 = i0 + 256;
    int v = 0;
    if (i0 < N_NODES) v += g_hist[i0];
    if (i1 < N_NODES) v += g_hist[i1];
    sm[t] = v;
    __syncthreads();
#pragma unroll
    for (int off = 128; off > 0; off >>= 1) {
        if (t < off) sm[t] += sm[t + off];
        __syncthreads();
    }
    if (t == 0) g_part[b] = sm[0];
}

__global__ void scan_b_kernel() {
    __shared__ int sm[256];
    int t = threadIdx.x;
    int v = (t < SCAN_BLOCKS) ? g_part[t] : 0;
    sm[t] = v;
    __syncthreads();
#pragma unroll
    for (int off = 1; off < 256; off <<= 1) {
        int add = (t >= off) ? sm[t - off] : 0;
        __syncthreads();
        sm[t] += add;
        __syncthreads();
    }
    if (t < SCAN_BLOCKS) g_part_scan[t] = sm[t] - v;
    if (t == 0) g_total = sm[255];
}

__global__ void scan_c_kernel() {
    __shared__ int sm[256];
    int b = blockIdx.x, t = threadIdx.x;
    int base = b * SCAN_CHUNK + 2 * t;
    int a0 = (base     < N_NODES) ? g_hist[base]     : 0;
    int a1 = (base + 1 < N_NODES) ? g_hist[base + 1] : 0;
    int s = a0 + a1;
    sm[t] = s;
    __syncthreads();
#pragma unroll
    for (int off = 1; off < 256; off <<= 1) {
        int add = (t >= off) ? sm[t - off] : 0;
        __syncthreads();
        sm[t] += add;
        __syncthreads();
    }
    int offset = g_part_scan[b] + sm[t] - s;
    if (base < N_NODES) {
        g_row_ptr[base] = offset;
        g_cursor[base]  = offset;
    }
    if (base + 1 < N_NODES) {
        g_row_ptr[base + 1] = offset + a0;
        g_cursor[base + 1]  = offset + a0;
    }
    if (b == 0 && t == 0) g_row_ptr[N_NODES] = g_total;
}

__global__ void fill_kernel(const int* __restrict__ srcs,
                            const int* __restrict__ dsts, int n_edges) {
    int e = blockIdx.x * blockDim.x + threadIdx.x;
    if (e >= n_edges) return;
    int s = __ldg(srcs + e);
    int d = __ldg(dsts + e);
    if ((unsigned)s >= N_NODES || (unsigned)d >= N_NODES) return;
    int pos = atomicAdd(g_cursor + d, 1);
    g_col[pos] = s;
}

// ---------------------------------------------------------------------------
// Aggregate layer 1: warp per node, mean of half x rows -> g_agg (fp32).
// Lane covers features [lane*4, lane*4+4) = one uint2 (4 halves).
// ---------------------------------------------------------------------------
__device__ __forceinline__ void acc_half4(float4& acc, uint2 u) {
    float2 f0 = __half22float2(*(__half2*)&u.x);
    float2 f1 = __half22float2(*(__half2*)&u.y);
    acc.x += f0.x; acc.y += f0.y; acc.z += f1.x; acc.w += f1.y;
}

__global__ void aggregate1_kernel() {
    int wid  = (blockIdx.x * blockDim.x + threadIdx.x) >> 5;
    int lane = threadIdx.x & 31;
    if (wid >= N_NODES) return;
    int beg = __ldg(g_row_ptr + wid), end = __ldg(g_row_ptr + wid + 1);

    float4 acc = make_float4(0.f, 0.f, 0.f, 0.f);
    int i = beg;
    for (; i + 4 <= end; i += 4) {
        int s0 = __ldg(g_col + i),     s1 = __ldg(g_col + i + 1);
        int s2 = __ldg(g_col + i + 2), s3 = __ldg(g_col + i + 3);
        uint2 u0 = __ldg((const uint2*)(g_xh + (size_t)s0 * 64) + lane);
        uint2 u1 = __ldg((const uint2*)(g_xh + (size_t)s1 * 64) + lane);
        uint2 u2 = __ldg((const uint2*)(g_xh + (size_t)s2 * 64) + lane);
        uint2 u3 = __ldg((const uint2*)(g_xh + (size_t)s3 * 64) + lane);
        acc_half4(acc, u0); acc_half4(acc, u1);
        acc_half4(acc, u2); acc_half4(acc, u3);
    }
    for (; i < end; i++) {
        int s = __ldg(g_col + i);
        uint2 u = __ldg((const uint2*)(g_xh + (size_t)s * 64) + lane);
        acc_half4(acc, u);
    }
    float inv = (end > beg) ? 1.0f / (float)(end - beg) : 1.0f;
    acc.x *= inv; acc.y *= inv; acc.z *= inv; acc.w *= inv;
    *((float4*)(g_agg + (size_t)wid * FEAT) + lane) = acc;
}

// ---------------------------------------------------------------------------
// TF32 tensor-core GEMMs with cp.async double buffering (BK=32, 2 stages).
// ---------------------------------------------------------------------------
#define SMST   36
#define TILE_F (128 * SMST)
#define STAGE_F (2 * TILE_F)
#define GSMEM_BYTES (2 * STAGE_F * 4)

#define MMA_TF32(c, a, b)                                                     \
    asm volatile("mma.sync.aligned.m16n8k8.row.col.f32.tf32.tf32.f32 "        \
                 "{%0,%1,%2,%3}, {%4,%5,%6,%7}, {%8,%9}, {%0,%1,%2,%3};"      \
                 : "+f"((c)[0]), "+f"((c)[1]), "+f"((c)[2]), "+f"((c)[3])     \
                 : "r"((a)[0]), "r"((a)[1]), "r"((a)[2]), "r"((a)[3]),        \
                   "r"((b)[0]), "r"((b)[1]))

__device__ __forceinline__ void cp_async16(unsigned saddr, const void* gptr, int ssize) {
    asm volatile("cp.async.cg.shared.global [%0], [%1], 16, %2;"
                 :: "r"(saddr), "l"(gptr), "r"(ssize));
}
__device__ __forceinline__ void cp_commit() {
    asm volatile("cp.async.commit_group;");
}
template <int N>
__device__ __forceinline__ void cp_wait() {
    asm volatile("cp.async.wait_group %0;" :: "n"(N));
}

__device__ __forceinline__ void mma_tile(const unsigned* As, const unsigned* Bs,
                                         int wm, int wn, int g, int tig,
                                         float acc[2][8][4]) {
#pragma unroll
    for (int ks = 0; ks < 4; ks++) {
        int k0 = ks * 8;
        unsigned afr[2][4], bfr[8][2];
#pragma unroll
        for (int mt = 0; mt < 2; mt++) {
            int r = wm * 32 + mt * 16 + g;
            afr[mt][0] = As[r * SMST + k0 + tig];
            afr[mt][1] = As[(r + 8) * SMST + k0 + tig];
            afr[mt][2] = As[r * SMST + k0 + tig + 4];
            afr[mt][3] = As[(r + 8) * SMST + k0 + tig + 4];
        }
#pragma unroll
        for (int nt = 0; nt < 8; nt++) {
            int c = wn * 64 + nt * 8 + g;
            bfr[nt][0] = Bs[c * SMST + k0 + tig];
            bfr[nt][1] = Bs[c * SMST + k0 + tig + 4];
        }
#pragma unroll
        for (int mt = 0; mt < 2; mt++)
#pragma unroll
            for (int nt = 0; nt < 8; nt++)
                MMA_TF32(acc[mt][nt], afr[mt], bfr[nt]);
    }
}

// GEMM1: h = relu([mean | x] @ [W1l; W1r]^T + b1l), K = 256 (concat).
__global__ __launch_bounds__(256, 2)
void gemm1_tc(const float* __restrict__ x,
              const float* __restrict__ W1l,
              const float* __restrict__ b1l,
              const float* __restrict__ W1r) {
    extern __shared__ float smem[];

    int t    = threadIdx.x;
    int lane = t & 31, w = t >> 5;
    int g    = lane >> 2, tig = lane & 3;
    int wm   = w & 3, wn = w >> 2;
    int m0   = blockIdx.x * 128;

    float acc[2][8][4];
#pragma unroll
    for (int mt = 0; mt < 2; mt++)
#pragma unroll
        for (int nt = 0; nt < 8; nt++)
#pragma unroll
            for (int i = 0; i < 4; i++) acc[mt][nt][i] = 0.f;

    unsigned sbase = (unsigned)__cvta_generic_to_shared(smem);

    auto copy_tile = [&](int tile, int buf) {
        int kt = tile * 32;
        const float* Asrc = (kt < 128) ? g_agg : x;
        int ak = (kt < 128) ? kt : kt - 128;
        const float* Wsrc = (kt < 128) ? W1l : W1r;
        unsigned abase = sbase + buf * STAGE_F * 4;
        unsigned bbase = abase + TILE_F * 4;
#pragma unroll
        for (int c = 0; c < 4; c++) {
            int cid = t * 4 + c;
            int row = cid >> 3, ch = cid & 7;
            int arow = m0 + row;
            int ssz = (arow < N_NODES) ? 16 : 0;
            int crow = (arow < N_NODES) ? arow : (N_NODES - 1);
            cp_async16(abase + (row * SMST + ch * 4) * 4,
                       Asrc + (size_t)crow * FEAT + ak + ch * 4, ssz);
            cp_async16(bbase + (row * SMST + ch * 4) * 4,
                       Wsrc + (size_t)row * FEAT + ak + ch * 4, 16);
        }
    };

    copy_tile(0, 0);
    cp_commit();

#pragma unroll 1
    for (int tile = 0; tile < 8; tile++) {
        if (tile + 1 < 8) {
            copy_tile(tile + 1, (tile + 1) & 1);
            cp_commit();
            cp_wait<1>();
        } else {
            cp_wait<0>();
        }
        __syncthreads();
        const unsigned* As = (const unsigned*)(smem + (tile & 1) * STAGE_F);
        const unsigned* Bs = As + TILE_F;
        mma_tile(As, Bs, wm, wn, g, tig, acc);
        __syncthreads();
    }

#pragma unroll
    for (int nt = 0; nt < 8; nt++) {
        int col = wn * 64 + nt * 8 + 2 * tig;
        float2 bias = __ldg((const float2*)(b1l + col));
#pragma unroll
        for (int mt = 0; mt < 2; mt++) {
            int r = m0 + wm * 32 + mt * 16 + g;
            if (r < N_NODES) {
                float2 o;
                o.x = fmaxf(acc[mt][nt][0] + bias.x, 0.f);
                o.y = fmaxf(acc[mt][nt][1] + bias.y, 0.f);
                *(float2*)(g_h + (size_t)r * FEAT + col) = o;
            }
            if (r + 8 < N_NODES) {
                float2 o;
                o.x = fmaxf(acc[mt][nt][2] + bias.x, 0.f);
                o.y = fmaxf(acc[mt][nt][3] + bias.y, 0.f);
                *(float2*)(g_h + (size_t)(r + 8) * FEAT + col) = o;
            }
        }
    }
}

// GEMM2: y = h @ [W2l; W2r]^T (K = 128). Cols <64 -> g_zh (half), >=64 -> g_r.
__global__ __launch_bounds__(256, 2)
void gemm2_tc(const float* __restrict__ W2l,
              const float* __restrict__ W2r) {
    extern __shared__ float smem[];

    int t    = threadIdx.x;
    int lane = t & 31, w = t >> 5;
    int g    = lane >> 2, tig = lane & 3;
    int wm   = w & 3, wn = w >> 2;
    int m0   = blockIdx.x * 128;

    float acc[2][8][4];
#pragma unroll
    for (int mt = 0; mt < 2; mt++)
#pragma unroll
        for (int nt = 0; nt < 8; nt++)
#pragma unroll
            for (int i = 0; i < 4; i++) acc[mt][nt][i] = 0.f;

    unsigned sbase = (unsigned)__cvta_generic_to_shared(smem);

    auto copy_tile = [&](int tile, int buf) {
        int kt = tile * 32;
        unsigned abase = sbase + buf * STAGE_F * 4;
        unsigned bbase = abase + TILE_F * 4;
#pragma unroll
        for (int c = 0; c < 4; c++) {
            int cid = t * 4 + c;
            int row = cid >> 3, ch = cid & 7;
            int arow = m0 + row;
            int ssz = (arow < N_NODES) ? 16 : 0;
            int crow = (arow < N_NODES) ? arow : (N_NODES - 1);
            cp_async16(abase + (row * SMST + ch * 4) * 4,
                       g_h + (size_t)crow * FEAT + kt + ch * 4, ssz);
            const float* Wrow = (row < 64) ? (W2l + (size_t)row * FEAT)
                                           : (W2r + (size_t)(row - 64) * FEAT);
            cp_async16(bbase + (row * SMST + ch * 4) * 4,
                       Wrow + kt + ch * 4, 16);
        }
    };

    copy_tile(0, 0);
    cp_commit();

#pragma unroll 1
    for (int tile = 0; tile < 4; tile++) {
        if (tile + 1 < 4) {
            copy_tile(tile + 1, (tile + 1) & 1);
            cp_commit();
            cp_wait<1>();
        } else {
            cp_wait<0>();
        }
        __syncthreads();
        const unsigned* As = (const unsigned*)(smem + (tile & 1) * STAGE_F);
        const unsigned* Bs = As + TILE_F;
        mma_tile(As, Bs, wm, wn, g, tig, acc);
        __syncthreads();
    }

#pragma unroll
    for (int nt = 0; nt < 8; nt++) {
        int col = wn * 64 + nt * 8 + 2 * tig;
#pragma unroll
        for (int mt = 0; mt < 2; mt++) {
            int r = m0 + wm * 32 + mt * 16 + g;
            if (col < 64) {
                if (r < N_NODES)
                    g_zh[(size_t)r * 32 + (col >> 1)] =
                        __floats2half2_rn(acc[mt][nt][0], acc[mt][nt][1]);
                if (r + 8 < N_NODES)
                    g_zh[(size_t)(r + 8) * 32 + (col >> 1)] =
                        __floats2half2_rn(acc[mt][nt][2], acc[mt][nt][3]);
            } else {
                int c2 = col - 64;
                if (r < N_NODES)
                    *(float2*)(g_r + (size_t)r * CLS + c2) =
                        make_float2(acc[mt][nt][0], acc[mt][nt][1]);
                if (r + 8 < N_NODES)
                    *(float2*)(g_r + (size_t)(r + 8) * CLS + c2) =
                        make_float2(acc[mt][nt][2], acc[mt][nt][3]);
            }
        }
    }
}

// ---------------------------------------------------------------------------
// Fused aggregate2 + bias + self-term + log_softmax + store. 16 lanes/node.
// Gathers half g_zh rows (128 B each).
// ---------------------------------------------------------------------------
__global__ void agg2_final_kernel(const float* __restrict__ b2l,
                                  float* __restrict__ out) {
    int gt   = blockIdx.x * blockDim.x + threadIdx.x;
    int node = gt >> 4;
    int lane = gt & 15;
    if (node >= N_NODES) return;
    int beg = __ldg(g_row_ptr + node), end = __ldg(g_row_ptr + node + 1);

    float4 acc = make_float4(0.f, 0.f, 0.f, 0.f);
    int i = beg;
    for (; i + 4 <= end; i += 4) {
        int s0 = __ldg(g_col + i),     s1 = __ldg(g_col + i + 1);
        int s2 = __ldg(g_col + i + 2), s3 = __ldg(g_col + i + 3);
        uint2 u0 = __ldg((const uint2*)(g_zh + (size_t)s0 * 32) + lane);
        uint2 u1 = __ldg((const uint2*)(g_zh + (size_t)s1 * 32) + lane);
        uint2 u2 = __ldg((const uint2*)(g_zh + (size_t)s2 * 32) + lane);
        uint2 u3 = __ldg((const uint2*)(g_zh + (size_t)s3 * 32) + lane);
        acc_half4(acc, u0); acc_half4(acc, u1);
        acc_half4(acc, u2); acc_half4(acc, u3);
    }
    for (; i < end; i++) {
        int s = __ldg(g_col + i);
        uint2 u = __ldg((const uint2*)(g_zh + (size_t)s * 32) + lane);
        acc_half4(acc, u);
    }
    float inv = (end > beg) ? 1.0f / (float)(end - beg) : 1.0f;

    float4 r  = *(const float4*)(g_r + (size_t)node * CLS + lane * 4);
    float4 bb = __ldg((const float4*)(b2l + lane * 4));

    float v[4];
    v[0] = acc.x * inv + bb.x + r.x;
    v[1] = acc.y * inv + bb.y + r.y;
    v[2] = acc.z * inv + bb.z + r.z;
    v[3] = acc.w * inv + bb.w + r.w;

    float rmax = fmaxf(fmaxf(v[0], v[1]), fmaxf(v[2], v[3]));
#pragma unroll
    for (int off = 8; off > 0; off >>= 1)
        rmax = fmaxf(rmax, __shfl_xor_sync(0xffffffffu, rmax, off));
    float s = expf(v[0] - rmax) + expf(v[1] - rmax)
            + expf(v[2] - rmax) + expf(v[3] - rmax);
#pragma unroll
    for (int off = 8; off > 0; off >>= 1)
        s += __shfl_xor_sync(0xffffffffu, s, off);
    float lse = logf(s) + rmax;

    float4 o;
    o.x = v[0] - lse; o.y = v[1] - lse; o.z = v[2] - lse; o.w = v[3] - lse;
    *(float4*)(out + (size_t)node * CLS + lane * 4) = o;
}

// ---------------------------------------------------------------------------
// Launch
// ---------------------------------------------------------------------------
extern "C" void kernel_launch(void* const* d_in, const int* in_sizes, int n_in,
                              void* d_out, int out_size) {
    const float* x    = (const float*)d_in[0];
    const int*   ei   = (const int*)d_in[1];
    const float* W1l  = (const float*)d_in[2];
    const float* b1l  = (const float*)d_in[3];
    const float* W1r  = (const float*)d_in[4];
    const float* W2l  = (const float*)d_in[5];
    const float* b2l  = (const float*)d_in[6];
    const float* W2r  = (const float*)d_in[7];
    float*       out  = (float*)d_out;

    const int n_edges = in_sizes[1] / 2;
    const int* srcs = ei;
    const int* dsts = ei + n_edges;

    const int edge_blocks = (n_edges + 255) / 256;
    const int conv_blocks = (N_NODES * 16 + 255) / 256;
    const int agg1_blocks = (N_NODES * 32 + 255) / 256;
    const int gemm_blocks = (N_NODES + 127) / 128;
    const int fin_blocks  = (N_NODES * 16 + 255) / 256;

    static int smem_set = 0;
    if (!smem_set) {
        cudaFuncSetAttribute(gemm1_tc, cudaFuncAttributeMaxDynamicSharedMemorySize, GSMEM_BYTES);
        cudaFuncSetAttribute(gemm2_tc, cudaFuncAttributeMaxDynamicSharedMemorySize, GSMEM_BYTES);
        smem_set = 1;
    }

    // Convert x to half + zero hist (fused), then CSR build
    convert_x_kernel<<<conv_blocks, 256>>>(x);
    hist_kernel<<<edge_blocks, 256>>>(srcs, dsts, n_edges);
    scan_a_kernel<<<SCAN_BLOCKS, 256>>>();
    scan_b_kernel<<<1, 256>>>();
    scan_c_kernel<<<SCAN_BLOCKS, 256>>>();
    fill_kernel<<<edge_blocks, 256>>>(srcs, dsts, n_edges);

    // Layer 1
    aggregate1_kernel<<<agg1_blocks, 256>>>();
    gemm1_tc<<<gemm_blocks, 256, GSMEM_BYTES>>>(x, W1l, b1l, W1r);

    // Layer 2
    gemm2_tc<<<gemm_blocks, 256, GSMEM_BYTES>>>(W2l, W2r);
    agg2_final_kernel<<<fin_blocks, 256>>>(b2l, out);
}

// round 8
// speedup vs baseline: 4.7727x; 1.0476x over previous
#include <cuda_runtime.h>
#include <cuda_fp16.h>

#define N_NODES 100000
#define FEAT    128
#define CLS     64
#define CAP     96     // max in-degree slots per node (P(overflow) ~ 1e-20 at mean 16)

// Scratch (allocation-free rule: __device__ globals; zero-initialized at load)
__device__ float   g_agg[(size_t)N_NODES * FEAT]; // layer-1 mean aggregation (fp32)
__device__ float   g_h[(size_t)N_NODES * FEAT];   // layer-1 activations
__device__ __half2 g_xh[(size_t)N_NODES * 64];    // x in half (128 halves/row)
__device__ __half2 g_zh[(size_t)N_NODES * 32];    // h @ W2l^T in half (64 halves/row)
__device__ float   g_r[(size_t)N_NODES * CLS];    // h @ W2r^T (self term, fp32)
__device__ int     g_deg[N_NODES];                // degree/cursor; re-zeroed each launch by agg2_final
__device__ int     g_col[(size_t)N_NODES * CAP];  // bucketed source indices

// ---------------------------------------------------------------------------
// k0: convert x -> half AND bucket edges by destination.
//   thread idx < N_NODES*16 : convert 8 floats of x
//   thread idx < n_edges    : pos = atomicAdd(deg[d]); col[d*CAP+pos] = s
// g_deg is guaranteed zero at launch start (static init / reset by agg2_final).
// ---------------------------------------------------------------------------
__global__ void convert_bucket_kernel(const float* __restrict__ x,
                                      const int* __restrict__ srcs,
                                      const int* __restrict__ dsts,
                                      int n_edges) {
    int idx = blockIdx.x * blockDim.x + threadIdx.x;
    const int n_conv = N_NODES * 16;
    if (idx < n_conv) {
        const float4* src = (const float4*)x + idx * 2;
        float4 a = __ldg(src), b = __ldg(src + 1);
        __half2 h0 = __floats2half2_rn(a.x, a.y);
        __half2 h1 = __floats2half2_rn(a.z, a.w);
        __half2 h2 = __floats2half2_rn(b.x, b.y);
        __half2 h3 = __floats2half2_rn(b.z, b.w);
        uint4 packed = make_uint4(*(unsigned*)&h0, *(unsigned*)&h1,
                                  *(unsigned*)&h2, *(unsigned*)&h3);
        *((uint4*)g_xh + idx) = packed;
    }
    if (idx < n_edges) {
        int s = __ldg(srcs + idx);
        int d = __ldg(dsts + idx);
        if ((unsigned)s < N_NODES && (unsigned)d < N_NODES) {
            int pos = atomicAdd(g_deg + d, 1);
            if (pos < CAP) g_col[(size_t)d * CAP + pos] = s;
        }
    }
}

// ---------------------------------------------------------------------------
// Aggregate layer 1: warp per node, mean of half x rows -> g_agg (fp32).
// ---------------------------------------------------------------------------
__device__ __forceinline__ void acc_half4(float4& acc, uint2 u) {
    float2 f0 = __half22float2(*(__half2*)&u.x);
    float2 f1 = __half22float2(*(__half2*)&u.y);
    acc.x += f0.x; acc.y += f0.y; acc.z += f1.x; acc.w += f1.y;
}

__global__ void aggregate1_kernel() {
    int wid  = (blockIdx.x * blockDim.x + threadIdx.x) >> 5;
    int lane = threadIdx.x & 31;
    if (wid >= N_NODES) return;
    int deg = __ldg(g_deg + wid);
    int len = min(deg, CAP);
    const int* cols = g_col + (size_t)wid * CAP;

    float4 acc = make_float4(0.f, 0.f, 0.f, 0.f);
    int i = 0;
    for (; i + 4 <= len; i += 4) {
        int4 s4 = *(const int4*)(cols + i);
        uint2 u0 = __ldg((const uint2*)(g_xh + (size_t)s4.x * 64) + lane);
        uint2 u1 = __ldg((const uint2*)(g_xh + (size_t)s4.y * 64) + lane);
        uint2 u2 = __ldg((const uint2*)(g_xh + (size_t)s4.z * 64) + lane);
        uint2 u3 = __ldg((const uint2*)(g_xh + (size_t)s4.w * 64) + lane);
        acc_half4(acc, u0); acc_half4(acc, u1);
        acc_half4(acc, u2); acc_half4(acc, u3);
    }
    for (; i < len; i++) {
        int s = __ldg(cols + i);
        uint2 u = __ldg((const uint2*)(g_xh + (size_t)s * 64) + lane);
        acc_half4(acc, u);
    }
    float inv = (deg > 0) ? 1.0f / (float)deg : 1.0f;
    acc.x *= inv; acc.y *= inv; acc.z *= inv; acc.w *= inv;
    *((float4*)(g_agg + (size_t)wid * FEAT) + lane) = acc;
}

// ---------------------------------------------------------------------------
// TF32 tensor-core GEMMs with cp.async double buffering (BK=32, 2 stages).
// ---------------------------------------------------------------------------
#define SMST   36
#define TILE_F (128 * SMST)
#define STAGE_F (2 * TILE_F)
#define GSMEM_BYTES (2 * STAGE_F * 4)

#define MMA_TF32(c, a, b)                                                     \
    asm volatile("mma.sync.aligned.m16n8k8.row.col.f32.tf32.tf32.f32 "        \
                 "{%0,%1,%2,%3}, {%4,%5,%6,%7}, {%8,%9}, {%0,%1,%2,%3};"      \
                 : "+f"((c)[0]), "+f"((c)[1]), "+f"((c)[2]), "+f"((c)[3])     \
                 : "r"((a)[0]), "r"((a)[1]), "r"((a)[2]), "r"((a)[3]),        \
                   "r"((b)[0]), "r"((b)[1]))

__device__ __forceinline__ void cp_async16(unsigned saddr, const void* gptr, int ssize) {
    asm volatile("cp.async.cg.shared.global [%0], [%1], 16, %2;"
                 :: "r"(saddr), "l"(gptr), "r"(ssize));
}
__device__ __forceinline__ void cp_commit() {
    asm volatile("cp.async.commit_group;");
}
template <int N>
__device__ __forceinline__ void cp_wait() {
    asm volatile("cp.async.wait_group %0;" :: "n"(N));
}

__device__ __forceinline__ void mma_tile(const unsigned* As, const unsigned* Bs,
                                         int wm, int wn, int g, int tig,
                                         float acc[2][8][4]) {
#pragma unroll
    for (int ks = 0; ks < 4; ks++) {
        int k0 = ks * 8;
        unsigned afr[2][4], bfr[8][2];
#pragma unroll
        for (int mt = 0; mt < 2; mt++) {
            int r = wm * 32 + mt * 16 + g;
            afr[mt][0] = As[r * SMST + k0 + tig];
            afr[mt][1] = As[(r + 8) * SMST + k0 + tig];
            afr[mt][2] = As[r * SMST + k0 + tig + 4];
            afr[mt][3] = As[(r + 8) * SMST + k0 + tig + 4];
        }
#pragma unroll
        for (int nt = 0; nt < 8; nt++) {
            int c = wn * 64 + nt * 8 + g;
            bfr[nt][0] = Bs[c * SMST + k0 + tig];
            bfr[nt][1] = Bs[c * SMST + k0 + tig + 4];
        }
#pragma unroll
        for (int mt = 0; mt < 2; mt++)
#pragma unroll
            for (int nt = 0; nt < 8; nt++)
                MMA_TF32(acc[mt][nt], afr[mt], bfr[nt]);
    }
}

// GEMM1: h = relu([mean | x] @ [W1l; W1r]^T + b1l), K = 256 (concat).
__global__ __launch_bounds__(256, 2)
void gemm1_tc(const float* __restrict__ x,
              const float* __restrict__ W1l,
              const float* __restrict__ b1l,
              const float* __restrict__ W1r) {
    extern __shared__ float smem[];

    int t    = threadIdx.x;
    int lane = t & 31, w = t >> 5;
    int g    = lane >> 2, tig = lane & 3;
    int wm   = w & 3, wn = w >> 2;
    int m0   = blockIdx.x * 128;

    float acc[2][8][4];
#pragma unroll
    for (int mt = 0; mt < 2; mt++)
#pragma unroll
        for (int nt = 0; nt < 8; nt++)
#pragma unroll
            for (int i = 0; i < 4; i++) acc[mt][nt][i] = 0.f;

    unsigned sbase = (unsigned)__cvta_generic_to_shared(smem);

    auto copy_tile = [&](int tile, int buf) {
        int kt = tile * 32;
        const float* Asrc = (kt < 128) ? g_agg : x;
        int ak = (kt < 128) ? kt : kt - 128;
        const float* Wsrc = (kt < 128) ? W1l : W1r;
        unsigned abase = sbase + buf * STAGE_F * 4;
        unsigned bbase = abase + TILE_F * 4;
#pragma unroll
        for (int c = 0; c < 4; c++) {
            int cid = t * 4 + c;
            int row = cid >> 3, ch = cid & 7;
            int arow = m0 + row;
            int ssz = (arow < N_NODES) ? 16 : 0;
            int crow = (arow < N_NODES) ? arow : (N_NODES - 1);
            cp_async16(abase + (row * SMST + ch * 4) * 4,
                       Asrc + (size_t)crow * FEAT + ak + ch * 4, ssz);
            cp_async16(bbase + (row * SMST + ch * 4) * 4,
                       Wsrc + (size_t)row * FEAT + ak + ch * 4, 16);
        }
    };

    copy_tile(0, 0);
    cp_commit();

#pragma unroll 1
    for (int tile = 0; tile < 8; tile++) {
        if (tile + 1 < 8) {
            copy_tile(tile + 1, (tile + 1) & 1);
            cp_commit();
            cp_wait<1>();
        } else {
            cp_wait<0>();
        }
        __syncthreads();
        const unsigned* As = (const unsigned*)(smem + (tile & 1) * STAGE_F);
        const unsigned* Bs = As + TILE_F;
        mma_tile(As, Bs, wm, wn, g, tig, acc);
        __syncthreads();
    }

#pragma unroll
    for (int nt = 0; nt < 8; nt++) {
        int col = wn * 64 + nt * 8 + 2 * tig;
        float2 bias = __ldg((const float2*)(b1l + col));
#pragma unroll
        for (int mt = 0; mt < 2; mt++) {
            int r = m0 + wm * 32 + mt * 16 + g;
            if (r < N_NODES) {
                float2 o;
                o.x = fmaxf(acc[mt][nt][0] + bias.x, 0.f);
                o.y = fmaxf(acc[mt][nt][1] + bias.y, 0.f);
                *(float2*)(g_h + (size_t)r * FEAT + col) = o;
            }
            if (r + 8 < N_NODES) {
                float2 o;
                o.x = fmaxf(acc[mt][nt][2] + bias.x, 0.f);
                o.y = fmaxf(acc[mt][nt][3] + bias.y, 0.f);
                *(float2*)(g_h + (size_t)(r + 8) * FEAT + col) = o;
            }
        }
    }
}

// GEMM2: y = h @ [W2l; W2r]^T (K = 128). Cols <64 -> g_zh (half), >=64 -> g_r.
__global__ __launch_bounds__(256, 2)
void gemm2_tc(const float* __restrict__ W2l,
              const float* __restrict__ W2r) {
    extern __shared__ float smem[];

    int t    = threadIdx.x;
    int lane = t & 31, w = t >> 5;
    int g    = lane >> 2, tig = lane & 3;
    int wm   = w & 3, wn = w >> 2;
    int m0   = blockIdx.x * 128;

    float acc[2][8][4];
#pragma unroll
    for (int mt = 0; mt < 2; mt++)
#pragma unroll
        for (int nt = 0; nt < 8; nt++)
#pragma unroll
            for (int i = 0; i < 4; i++) acc[mt][nt][i] = 0.f;

    unsigned sbase = (unsigned)__cvta_generic_to_shared(smem);

    auto copy_tile = [&](int tile, int buf) {
        int kt = tile * 32;
        unsigned abase = sbase + buf * STAGE_F * 4;
        unsigned bbase = abase + TILE_F * 4;
#pragma unroll
        for (int c = 0; c < 4; c++) {
            int cid = t * 4 + c;
            int row = cid >> 3, ch = cid & 7;
            int arow = m0 + row;
            int ssz = (arow < N_NODES) ? 16 : 0;
            int crow = (arow < N_NODES) ? arow : (N_NODES - 1);
            cp_async16(abase + (row * SMST + ch * 4) * 4,
                       g_h + (size_t)crow * FEAT + kt + ch * 4, ssz);
            const float* Wrow = (row < 64) ? (W2l + (size_t)row * FEAT)
                                           : (W2r + (size_t)(row - 64) * FEAT);
            cp_async16(bbase + (row * SMST + ch * 4) * 4,
                       Wrow + kt + ch * 4, 16);
        }
    };

    copy_tile(0, 0);
    cp_commit();

#pragma unroll 1
    for (int tile = 0; tile < 4; tile++) {
        if (tile + 1 < 4) {
            copy_tile(tile + 1, (tile + 1) & 1);
            cp_commit();
            cp_wait<1>();
        } else {
            cp_wait<0>();
        }
        __syncthreads();
        const unsigned* As = (const unsigned*)(smem + (tile & 1) * STAGE_F);
        const unsigned* Bs = As + TILE_F;
        mma_tile(As, Bs, wm, wn, g, tig, acc);
        __syncthreads();
    }

#pragma unroll
    for (int nt = 0; nt < 8; nt++) {
        int col = wn * 64 + nt * 8 + 2 * tig;
#pragma unroll
        for (int mt = 0; mt < 2; mt++) {
            int r = m0 + wm * 32 + mt * 16 + g;
            if (col < 64) {
                if (r < N_NODES)
                    g_zh[(size_t)r * 32 + (col >> 1)] =
                        __floats2half2_rn(acc[mt][nt][0], acc[mt][nt][1]);
                if (r + 8 < N_NODES)
                    g_zh[(size_t)(r + 8) * 32 + (col >> 1)] =
                        __floats2half2_rn(acc[mt][nt][2], acc[mt][nt][3]);
            } else {
                int c2 = col - 64;
                if (r < N_NODES)
                    *(float2*)(g_r + (size_t)r * CLS + c2) =
                        make_float2(acc[mt][nt][0], acc[mt][nt][1]);
                if (r + 8 < N_NODES)
                    *(float2*)(g_r + (size_t)(r + 8) * CLS + c2) =
                        make_float2(acc[mt][nt][2], acc[mt][nt][3]);
            }
        }
    }
}

// ---------------------------------------------------------------------------
// Fused aggregate2 + bias + self-term + log_softmax + store. 16 lanes/node.
// Also resets g_deg to 0 for the next launch (invariant restore).
// ---------------------------------------------------------------------------
__global__ void agg2_final_kernel(const float* __restrict__ b2l,
                                  float* __restrict__ out) {
    int gt   = blockIdx.x * blockDim.x + threadIdx.x;
    int node = gt >> 4;
    int lane = gt & 15;
    if (node >= N_NODES) return;
    int deg = __ldg(g_deg + node);
    int len = min(deg, CAP);
    const int* cols = g_col + (size_t)node * CAP;

    float4 acc = make_float4(0.f, 0.f, 0.f, 0.f);
    int i = 0;
    for (; i + 4 <= len; i += 4) {
        int4 s4 = *(const int4*)(cols + i);
        uint2 u0 = __ldg((const uint2*)(g_zh + (size_t)s4.x * 32) + lane);
        uint2 u1 = __ldg((const uint2*)(g_zh + (size_t)s4.y * 32) + lane);
        uint2 u2 = __ldg((const uint2*)(g_zh + (size_t)s4.z * 32) + lane);
        uint2 u3 = __ldg((const uint2*)(g_zh + (size_t)s4.w * 32) + lane);
        acc_half4(acc, u0); acc_half4(acc, u1);
        acc_half4(acc, u2); acc_half4(acc, u3);
    }
    for (; i < len; i++) {
        int s = __ldg(cols + i);
        uint2 u = __ldg((const uint2*)(g_zh + (size_t)s * 32) + lane);
        acc_half4(acc, u);
    }
    float inv = (deg > 0) ? 1.0f / (float)deg : 1.0f;

    float4 r  = *(const float4*)(g_r + (size_t)node * CLS + lane * 4);
    float4 bb = __ldg((const float4*)(b2l + lane * 4));

    float v[4];
    v[0] = acc.x * inv + bb.x + r.x;
    v[1] = acc.y * inv + bb.y + r.y;
    v[2] = acc.z * inv + bb.z + r.z;
    v[3] = acc.w * inv + bb.w + r.w;

    float rmax = fmaxf(fmaxf(v[0], v[1]), fmaxf(v[2], v[3]));
#pragma unroll
    for (int off = 8; off > 0; off >>= 1)
        rmax = fmaxf(rmax, __shfl_xor_sync(0xffffffffu, rmax, off));
    float s = expf(v[0] - rmax) + expf(v[1] - rmax)
            + expf(v[2] - rmax) + expf(v[3] - rmax);
#pragma unroll
    for (int off = 8; off > 0; off >>= 1)
        s += __shfl_xor_sync(0xffffffffu, s, off);
    float lse = logf(s) + rmax;

    float4 o;
    o.x = v[0] - lse; o.y = v[1] - lse; o.z = v[2] - lse; o.w = v[3] - lse;
    *(float4*)(out + (size_t)node * CLS + lane * 4) = o;

    // restore launch-start invariant for graph replay
    if (lane == 0) g_deg[node] = 0;
}

// ---------------------------------------------------------------------------
// Launch (5 kernels)
// ---------------------------------------------------------------------------
extern "C" void kernel_launch(void* const* d_in, const int* in_sizes, int n_in,
                              void* d_out, int out_size) {
    const float* x    = (const float*)d_in[0];
    const int*   ei   = (const int*)d_in[1];
    const float* W1l  = (const float*)d_in[2];
    const float* b1l  = (const float*)d_in[3];
    const float* W1r  = (const float*)d_in[4];
    const float* W2l  = (const float*)d_in[5];
    const float* b2l  = (const float*)d_in[6];
    const float* W2r  = (const float*)d_in[7];
    float*       out  = (float*)d_out;

    const int n_edges = in_sizes[1] / 2;
    const int* srcs = ei;
    const int* dsts = ei + n_edges;

    int cb_threads = N_NODES * 16;
    if (n_edges > cb_threads) cb_threads = n_edges;
    const int cb_blocks   = (cb_threads + 255) / 256;
    const int agg1_blocks = (N_NODES * 32 + 255) / 256;
    const int gemm_blocks = (N_NODES + 127) / 128;
    const int fin_blocks  = (N_NODES * 16 + 255) / 256;

    cudaFuncSetAttribute(gemm1_tc, cudaFuncAttributeMaxDynamicSharedMemorySize, GSMEM_BYTES);
    cudaFuncSetAttribute(gemm2_tc, cudaFuncAttributeMaxDynamicSharedMemorySize, GSMEM_BYTES);

    convert_bucket_kernel<<<cb_blocks, 256>>>(x, srcs, dsts, n_edges);
    aggregate1_kernel<<<agg1_blocks, 256>>>();
    gemm1_tc<<<gemm_blocks, 256, GSMEM_BYTES>>>(x, W1l, b1l, W1r);
    gemm2_tc<<<gemm_blocks, 256, GSMEM_BYTES>>>(W2l, W2r);
    agg2_final_kernel<<<fin_blocks, 256>>>(b2l, out);
}

// round 11
// speedup vs baseline: 6.0628x; 1.2703x over previous
#include <cuda_runtime.h>
#include <cuda_fp16.h>

#define N_NODES 100000
#define FEAT    128
#define CLS     64
#define CAP     96     // max in-degree slots per node (P(overflow) ~ 1e-20 at mean 16)

// Scratch (allocation-free rule: __device__ globals; zero-initialized at load)
__device__ __half2 g_xh[(size_t)N_NODES * 64];     // x in half (128 halves/row)
__device__ __half2 g_aggh[(size_t)N_NODES * 64];   // layer-1 mean (half)
__device__ __half2 g_hh[(size_t)N_NODES * 64];     // layer-1 activations (half)
__device__ __half2 g_zh[(size_t)N_NODES * 32];     // h @ W2l^T (half)
__device__ float   g_r[(size_t)N_NODES * CLS];     // h @ W2r^T (self term, fp32)
__device__ __half  g_w1h[128 * 256];               // [n][k] : k<128 W1l, k>=128 W1r
__device__ __half  g_w2h[128 * 128];               // [n][k] : n<64 W2l, n>=64 W2r
__device__ int     g_deg[N_NODES];                 // degree; re-zeroed by agg2_final
__device__ int     g_col[(size_t)N_NODES * CAP];   // bucketed source indices

// ---------------------------------------------------------------------------
// k0: convert x -> half, convert weights -> half, bucket edges by destination.
// ---------------------------------------------------------------------------
__global__ void convert_bucket_kernel(const float* __restrict__ x,
                                      const int* __restrict__ srcs,
                                      const int* __restrict__ dsts,
                                      const float* __restrict__ W1l,
                                      const float* __restrict__ W1r,
                                      const float* __restrict__ W2l,
                                      const float* __restrict__ W2r,
                                      int n_edges) {
    int idx = blockIdx.x * blockDim.x + threadIdx.x;
    const int n_conv = N_NODES * 16;
    if (idx < n_conv) {
        const float4* src = (const float4*)x + idx * 2;
        float4 a = __ldg(src), b = __ldg(src + 1);
        __half2 h0 = __floats2half2_rn(a.x, a.y);
        __half2 h1 = __floats2half2_rn(a.z, a.w);
        __half2 h2 = __floats2half2_rn(b.x, b.y);
        __half2 h3 = __floats2half2_rn(b.z, b.w);
        *((uint4*)g_xh + idx) = make_uint4(*(unsigned*)&h0, *(unsigned*)&h1,
                                           *(unsigned*)&h2, *(unsigned*)&h3);
    }
    // W1 interleave: g_w1h row n (256 halves) = [W1l[n][0..128) | W1r[n][0..128)]
    if (idx < 4096) {                       // 128 rows * 32 chunks of 8
        int n = idx >> 5, cr = idx & 31;
        const float* src = (cr < 16) ? (W1l + n * 128 + cr * 8)
                                     : (W1r + n * 128 + (cr - 16) * 8);
        float4 a = __ldg((const float4*)src), b = __ldg((const float4*)src + 1);
        __half2 h0 = __floats2half2_rn(a.x, a.y);
        __half2 h1 = __floats2half2_rn(a.z, a.w);
        __half2 h2 = __floats2half2_rn(b.x, b.y);
        __half2 h3 = __floats2half2_rn(b.z, b.w);
        *((uint4*)(g_w1h + n * 256) + cr) = make_uint4(*(unsigned*)&h0, *(unsigned*)&h1,
                                                       *(unsigned*)&h2, *(unsigned*)&h3);
    }
    // W2 interleave: g_w2h row n = (n<64 ? W2l[n] : W2r[n-64])
    if (idx < 2048) {                       // 128 rows * 16 chunks of 8
        int n = idx >> 4, cr = idx & 15;
        const float* src = (n < 64) ? (W2l + n * 128 + cr * 8)
                                    : (W2r + (n - 64) * 128 + cr * 8);
        float4 a = __ldg((const float4*)src), b = __ldg((const float4*)src + 1);
        __half2 h0 = __floats2half2_rn(a.x, a.y);
        __half2 h1 = __floats2half2_rn(a.z, a.w);
        __half2 h2 = __floats2half2_rn(b.x, b.y);
        __half2 h3 = __floats2half2_rn(b.z, b.w);
        *((uint4*)(g_w2h + n * 128) + cr) = make_uint4(*(unsigned*)&h0, *(unsigned*)&h1,
                                                       *(unsigned*)&h2, *(unsigned*)&h3);
    }
    if (idx < n_edges) {
        int s = __ldg(srcs + idx);
        int d = __ldg(dsts + idx);
        if ((unsigned)s < N_NODES && (unsigned)d < N_NODES) {
            int pos = atomicAdd(g_deg + d, 1);
            if (pos < CAP) g_col[(size_t)d * CAP + pos] = s;
        }
    }
}

// ---------------------------------------------------------------------------
// Aggregate layer 1: warp per node, mean of half x rows -> g_aggh (half).
// ---------------------------------------------------------------------------
__device__ __forceinline__ void acc_half4(float4& acc, uint2 u) {
    float2 f0 = __half22float2(*(__half2*)&u.x);
    float2 f1 = __half22float2(*(__half2*)&u.y);
    acc.x += f0.x; acc.y += f0.y; acc.z += f1.x; acc.w += f1.y;
}

__global__ void aggregate1_kernel() {
    int wid  = (blockIdx.x * blockDim.x + threadIdx.x) >> 5;
    int lane = threadIdx.x & 31;
    if (wid >= N_NODES) return;
    int deg = __ldg(g_deg + wid);
    int len = min(deg, CAP);
    const int* cols = g_col + (size_t)wid * CAP;

    float4 acc = make_float4(0.f, 0.f, 0.f, 0.f);
    int i = 0;
    for (; i + 4 <= len; i += 4) {
        int4 s4 = *(const int4*)(cols + i);
        uint2 u0 = __ldg((const uint2*)(g_xh + (size_t)s4.x * 64) + lane);
        uint2 u1 = __ldg((const uint2*)(g_xh + (size_t)s4.y * 64) + lane);
        uint2 u2 = __ldg((const uint2*)(g_xh + (size_t)s4.z * 64) + lane);
        uint2 u3 = __ldg((const uint2*)(g_xh + (size_t)s4.w * 64) + lane);
        acc_half4(acc, u0); acc_half4(acc, u1);
        acc_half4(acc, u2); acc_half4(acc, u3);
    }
    for (; i < len; i++) {
        int s = __ldg(cols + i);
        uint2 u = __ldg((const uint2*)(g_xh + (size_t)s * 64) + lane);
        acc_half4(acc, u);
    }
    float inv = (deg > 0) ? 1.0f / (float)deg : 1.0f;
    __half2 o0 = __floats2half2_rn(acc.x * inv, acc.y * inv);
    __half2 o1 = __floats2half2_rn(acc.z * inv, acc.w * inv);
    *((uint2*)(g_aggh + (size_t)wid * 64) + lane) =
        make_uint2(*(unsigned*)&o0, *(unsigned*)&o1);
}

// ---------------------------------------------------------------------------
// FP16 tensor-core GEMMs (m16n8k16, fp32 accum), cp.async double buffering.
//   Block 128x128, 8 warps (4Mx2N), warp tile 32x64, BK=64 halves, 2 stages.
//   smem rows: 64 halves padded to 72 (= 36 uints) -> conflict-free frags.
// ---------------------------------------------------------------------------
#define SMST   36                       // uints per smem row
#define TILE_U (128 * SMST)             // uints per tile (4608)
#define STAGE_U (2 * TILE_U)
#define GSMEM_BYTES (2 * STAGE_U * 4)   // 73728

#define MMA_F16(c, a, b)                                                      \
    asm volatile("mma.sync.aligned.m16n8k16.row.col.f32.f16.f16.f32 "         \
                 "{%0,%1,%2,%3}, {%4,%5,%6,%7}, {%8,%9}, {%0,%1,%2,%3};"      \
                 : "+f"((c)[0]), "+f"((c)[1]), "+f"((c)[2]), "+f"((c)[3])     \
                 : "r"((a)[0]), "r"((a)[1]), "r"((a)[2]), "r"((a)[3]),        \
                   "r"((b)[0]), "r"((b)[1]))

__device__ __forceinline__ void cp_async16(unsigned saddr, const void* gptr) {
    asm volatile("cp.async.cg.shared.global [%0], [%1], 16;"
                 :: "r"(saddr), "l"(gptr));
}
__device__ __forceinline__ void cp_commit() {
    asm volatile("cp.async.commit_group;");
}
template <int N>
__device__ __forceinline__ void cp_wait() {
    asm volatile("cp.async.wait_group %0;" :: "n"(N));
}

// one BK=64-halves tile of MMAs: 4 k16 steps
__device__ __forceinline__ void mma_tile(const unsigned* As, const unsigned* Bs,
                                         int wm, int wn, int g, int tig,
                                         float acc[2][8][4]) {
#pragma unroll
    for (int ks = 0; ks < 4; ks++) {
        int k0 = ks * 8;                 // uint offset (16 halves = 8 uints)
        unsigned afr[2][4], bfr[8][2];
#pragma unroll
        for (int mt = 0; mt < 2; mt++) {
            int r = wm * 32 + mt * 16 + g;
            afr[mt][0] = As[r * SMST + k0 + tig];
            afr[mt][1] = As[(r + 8) * SMST + k0 + tig];
            afr[mt][2] = As[r * SMST + k0 + tig + 4];
            afr[mt][3] = As[(r + 8) * SMST + k0 + tig + 4];
        }
#pragma unroll
        for (int nt = 0; nt < 8; nt++) {
            int c = wn * 64 + nt * 8 + g;
            bfr[nt][0] = Bs[c * SMST + k0 + tig];
            bfr[nt][1] = Bs[c * SMST + k0 + tig + 4];
        }
#pragma unroll
        for (int mt = 0; mt < 2; mt++)
#pragma unroll
            for (int nt = 0; nt < 8; nt++)
                MMA_F16(acc[mt][nt], afr[mt], bfr[nt]);
    }
}

// GEMM1: h = relu([mean | x] @ [W1l; W1r]^T + b1l), K = 256 halves (4 k-tiles).
__global__ __launch_bounds__(256, 2)
void gemm1_tc(const float* __restrict__ b1l) {
    extern __shared__ unsigned smem[];

    int t    = threadIdx.x;
    int lane = t & 31, w = t >> 5;
    int g    = lane >> 2, tig = lane & 3;
    int wm   = w & 3, wn = w >> 2;
    int m0   = blockIdx.x * 128;

    float acc[2][8][4];
#pragma unroll
    for (int mt = 0; mt < 2; mt++)
#pragma unroll
        for (int nt = 0; nt < 8; nt++)
#pragma unroll
            for (int i = 0; i < 4; i++) acc[mt][nt][i] = 0.f;

    unsigned sbase = (unsigned)__cvta_generic_to_shared(smem);

    // tile = 0..3, each covers 64 halves of the 256-half concat K
    auto copy_tile = [&](int tile, int buf) {
        const __half2* Asrc = (tile < 2) ? g_aggh : g_xh;
        int ah2 = (tile & 1) * 32;               // half2 offset within row
        unsigned abase = sbase + buf * STAGE_U * 4;
        unsigned bbase = abase + TILE_U * 4;
#pragma unroll
        for (int c = 0; c < 4; c++) {
            int cid = t * 4 + c;                 // 0..1023
            int row = cid >> 3, ch = cid & 7;    // 8 x 16B chunks per row
            int arow = m0 + row;
            int crow = (arow < N_NODES) ? arow : (N_NODES - 1);
            cp_async16(abase + (row * SMST + ch * 4) * 4,
                       Asrc + (size_t)crow * 64 + ah2 + ch * 4);
            cp_async16(bbase + (row * SMST + ch * 4) * 4,
                       g_w1h + (size_t)row * 256 + tile * 64 + ch * 8);
        }
    };

    copy_tile(0, 0);
    cp_commit();

#pragma unroll 1
    for (int tile = 0; tile < 4; tile++) {
        if (tile + 1 < 4) {
            copy_tile(tile + 1, (tile + 1) & 1);
            cp_commit();
            cp_wait<1>();
        } else {
            cp_wait<0>();
        }
        __syncthreads();
        const unsigned* As = smem + (tile & 1) * STAGE_U;
        const unsigned* Bs = As + TILE_U;
        mma_tile(As, Bs, wm, wn, g, tig, acc);
        __syncthreads();
    }

    // Epilogue: bias + relu -> g_hh (half)
#pragma unroll
    for (int nt = 0; nt < 8; nt++) {
        int col = wn * 64 + nt * 8 + 2 * tig;
        float2 bias = __ldg((const float2*)(b1l + col));
#pragma unroll
        for (int mt = 0; mt < 2; mt++) {
            int r = m0 + wm * 32 + mt * 16 + g;
            if (r < N_NODES) {
                __half2 o = __floats2half2_rn(
                    fmaxf(acc[mt][nt][0] + bias.x, 0.f),
                    fmaxf(acc[mt][nt][1] + bias.y, 0.f));
                g_hh[(size_t)r * 64 + (col >> 1)] = o;
            }
            if (r + 8 < N_NODES) {
                __half2 o = __floats2half2_rn(
                    fmaxf(acc[mt][nt][2] + bias.x, 0.f),
                    fmaxf(acc[mt][nt][3] + bias.y, 0.f));
                g_hh[(size_t)(r + 8) * 64 + (col >> 1)] = o;
            }
        }
    }
}

// GEMM2: y = h @ [W2l; W2r]^T (K = 128 halves, 2 k-tiles).
// Cols <64 -> g_zh (half), >=64 -> g_r (fp32).
__global__ __launch_bounds__(256, 2)
void gemm2_tc() {
    extern __shared__ unsigned smem[];

    int t    = threadIdx.x;
    int lane = t & 31, w = t >> 5;
    int g    = lane >> 2, tig = lane & 3;
    int wm   = w & 3, wn = w >> 2;
    int m0   = blockIdx.x * 128;

    float acc[2][8][4];
#pragma unroll
    for (int mt = 0; mt < 2; mt++)
#pragma unroll
        for (int nt = 0; nt < 8; nt++)
#pragma unroll
            for (int i = 0; i < 4; i++) acc[mt][nt][i] = 0.f;

    unsigned sbase = (unsigned)__cvta_generic_to_shared(smem);

    auto copy_tile = [&](int tile, int buf) {
        int ah2 = tile * 32;
        unsigned abase = sbase + buf * STAGE_U * 4;
        unsigned bbase = abase + TILE_U * 4;
#pragma unroll
        for (int c = 0; c < 4; c++) {
            int cid = t * 4 + c;
            int row = cid >> 3, ch = cid & 7;
            int arow = m0 + row;
            int crow = (arow < N_NODES) ? arow : (N_NODES - 1);
            cp_async16(abase + (row * SMST + ch * 4) * 4,
                       g_hh + (size_t)crow * 64 + ah2 + ch * 4);
            cp_async16(bbase + (row * SMST + ch * 4) * 4,
                       g_w2h + (size_t)row * 128 + tile * 64 + ch * 8);
        }
    };

    copy_tile(0, 0);
    cp_commit();

#pragma unroll 1
    for (int tile = 0; tile < 2; tile++) {
        if (tile + 1 < 2) {
            copy_tile(tile + 1, 1);
            cp_commit();
            cp_wait<1>();
        } else {
            cp_wait<0>();
        }
        __syncthreads();
        const unsigned* As = smem + (tile & 1) * STAGE_U;
        const unsigned* Bs = As + TILE_U;
        mma_tile(As, Bs, wm, wn, g, tig, acc);
        __syncthreads();
    }

#pragma unroll
    for (int nt = 0; nt < 8; nt++) {
        int col = wn * 64 + nt * 8 + 2 * tig;
#pragma unroll
        for (int mt = 0; mt < 2; mt++) {
            int r = m0 + wm * 32 + mt * 16 + g;
            if (col < 64) {
                if (r < N_NODES)
                    g_zh[(size_t)r * 32 + (col >> 1)] =
                        __floats2half2_rn(acc[mt][nt][0], acc[mt][nt][1]);
                if (r + 8 < N_NODES)
                    g_zh[(size_t)(r + 8) * 32 + (col >> 1)] =
                        __floats2half2_rn(acc[mt][nt][2], acc[mt][nt][3]);
            } else {
                int c2 = col - 64;
                if (r < N_NODES)
                    *(float2*)(g_r + (size_t)r * CLS + c2) =
                        make_float2(acc[mt][nt][0], acc[mt][nt][1]);
                if (r + 8 < N_NODES)
                    *(float2*)(g_r + (size_t)(r + 8) * CLS + c2) =
                        make_float2(acc[mt][nt][2], acc[mt][nt][3]);
            }
        }
    }
}

// ---------------------------------------------------------------------------
// Fused aggregate2 + bias + self-term + log_softmax + store. 16 lanes/node.
// Also resets g_deg to 0 for the next launch (invariant restore).
// ---------------------------------------------------------------------------
__global__ void agg2_final_kernel(const float* __restrict__ b2l,
                                  float* __restrict__ out) {
    int gt   = blockIdx.x * blockDim.x + threadIdx.x;
    int node = gt >> 4;
    int lane = gt & 15;
    if (node >= N_NODES) return;
    int deg = __ldg(g_deg + node);
    int len = min(deg, CAP);
    const int* cols = g_col + (size_t)node * CAP;

    float4 acc = make_float4(0.f, 0.f, 0.f, 0.f);
    int i = 0;
    for (; i + 4 <= len; i += 4) {
        int4 s4 = *(const int4*)(cols + i);
        uint2 u0 = __ldg((const uint2*)(g_zh + (size_t)s4.x * 32) + lane);
        uint2 u1 = __ldg((const uint2*)(g_zh + (size_t)s4.y * 32) + lane);
        uint2 u2 = __ldg((const uint2*)(g_zh + (size_t)s4.z * 32) + lane);
        uint2 u3 = __ldg((const uint2*)(g_zh + (size_t)s4.w * 32) + lane);
        acc_half4(acc, u0); acc_half4(acc, u1);
        acc_half4(acc, u2); acc_half4(acc, u3);
    }
    for (; i < len; i++) {
        int s = __ldg(cols + i);
        uint2 u = __ldg((const uint2*)(g_zh + (size_t)s * 32) + lane);
        acc_half4(acc, u);
    }
    float inv = (deg > 0) ? 1.0f / (float)deg : 1.0f;

    float4 r  = *(const float4*)(g_r + (size_t)node * CLS + lane * 4);
    float4 bb = __ldg((const float4*)(b2l + lane * 4));

    float v[4];
    v[0] = acc.x * inv + bb.x + r.x;
    v[1] = acc.y * inv + bb.y + r.y;
    v[2] = acc.z * inv + bb.z + r.z;
    v[3] = acc.w * inv + bb.w + r.w;

    float rmax = fmaxf(fmaxf(v[0], v[1]), fmaxf(v[2], v[3]));
#pragma unroll
    for (int off = 8; off > 0; off >>= 1)
        rmax = fmaxf(rmax, __shfl_xor_sync(0xffffffffu, rmax, off));
    float s = expf(v[0] - rmax) + expf(v[1] - rmax)
            + expf(v[2] - rmax) + expf(v[3] - rmax);
#pragma unroll
    for (int off = 8; off > 0; off >>= 1)
        s += __shfl_xor_sync(0xffffffffu, s, off);
    float lse = logf(s) + rmax;

    float4 o;
    o.x = v[0] - lse; o.y = v[1] - lse; o.z = v[2] - lse; o.w = v[3] - lse;
    *(float4*)(out + (size_t)node * CLS + lane * 4) = o;

    if (lane == 0) g_deg[node] = 0;   // restore launch-start invariant
}

// ---------------------------------------------------------------------------
// Launch (5 kernels)
// ---------------------------------------------------------------------------
extern "C" void kernel_launch(void* const* d_in, const int* in_sizes, int n_in,
                              void* d_out, int out_size) {
    const float* x    = (const float*)d_in[0];
    const int*   ei   = (const int*)d_in[1];
    const float* W1l  = (const float*)d_in[2];
    const float* b1l  = (const float*)d_in[3];
    const float* W1r  = (const float*)d_in[4];
    const float* W2l  = (const float*)d_in[5];
    const float* b2l  = (const float*)d_in[6];
    const float* W2r  = (const float*)d_in[7];
    float*       out  = (float*)d_out;

    const int n_edges = in_sizes[1] / 2;
    const int* srcs = ei;
    const int* dsts = ei + n_edges;

    int cb_threads = N_NODES * 16;
    if (n_edges > cb_threads) cb_threads = n_edges;
    const int cb_blocks   = (cb_threads + 255) / 256;
    const int agg1_blocks = (N_NODES * 32 + 255) / 256;
    const int gemm_blocks = (N_NODES + 127) / 128;
    const int fin_blocks  = (N_NODES * 16 + 255) / 256;

    cudaFuncSetAttribute(gemm1_tc, cudaFuncAttributeMaxDynamicSharedMemorySize, GSMEM_BYTES);
    cudaFuncSetAttribute(gemm2_tc, cudaFuncAttributeMaxDynamicSharedMemorySize, GSMEM_BYTES);

    convert_bucket_kernel<<<cb_blocks, 256>>>(x, srcs, dsts, W1l, W1r, W2l, W2r, n_edges);
    aggregate1_kernel<<<agg1_blocks, 256>>>();
    gemm1_tc<<<gemm_blocks, 256, GSMEM_BYTES>>>(b1l);
    gemm2_tc<<<gemm_blocks, 256, GSMEM_BYTES>>>();
    agg2_final_kernel<<<fin_blocks, 256>>>(b2l, out);
}